// round 4
// baseline (speedup 1.0000x reference)
#include <cuda_runtime.h>
#include <cuda_bf16.h>

// ---------------------------------------------------------------------------
// JointRetriveDeformHead — round 4
//  * k_transpose: var/rsc -> [k][s] layout for coalesced distance kernel.
//  * k_prepack: duplicate-pair (f32x2) weight banks for pointnet H2/H3 and
//    decoder H2 (removes per-iter MOV pair-duplication).
//  * k_dist: thread-per-4-sources sequential-k distances (no shuffles),
//    exact top-10 kept.
//  * k_preSC1: 8 sources/block (8x weight reuse); k_preP1 separate.
//  * pointnet/decode inner loops: broadcast LDS.128 activation pairs +
//    LDG.128 duplicated weight pairs.
// ---------------------------------------------------------------------------

#define B_      64
#define S_      1024
#define D_      256
#define KRET    10
#define NPART   16
#define NPAR    96
#define PSRC3   1536
#define NQ      8

__device__ float g_pool[NQ * 2 * B_ * D_];
__device__ float g_ret [B_ * D_];
__device__ float g_T   [B_ * D_];
__device__ int   g_idx [B_ * KRET];
__device__ float g_par [B_ * KRET * NPAR];
__device__ float g_SC1 [S_ * D_];
__device__ float g_P1  [S_ * NPART * D_];
__device__ float g_varT[D_ * S_];            // [k][s]
__device__ float g_rscT[D_ * S_];            // [k][s]

typedef unsigned long long u64;

__device__ u64 g_W2d[2 * 64 * 128];          // dup pairs per encoder
__device__ u64 g_W3d[2 * 128 * 256];
__device__ u64 g_dW2d[256 * 256];

__device__ __forceinline__ u64 pk(float lo, float hi) {
    u64 r; asm("mov.b64 %0,{%1,%2};" : "=l"(r) : "f"(lo), "f"(hi)); return r;
}
__device__ __forceinline__ void upk(u64 v, float& lo, float& hi) {
    asm("mov.b64 {%0,%1},%2;" : "=f"(lo), "=f"(hi) : "l"(v));
}
__device__ __forceinline__ u64 fma2(u64 a, u64 b, u64 c) {
    u64 d; asm("fma.rn.f32x2 %0,%1,%2,%3;" : "=l"(d) : "l"(a), "l"(b), "l"(c)); return d;
}

// ---------------------------------------------------------------------------
// Kernel A: transpose var & rsc to [k][s]. grid (32,8), block (32,8).
// ---------------------------------------------------------------------------
__global__ __launch_bounds__(256)
void k_transpose(const float* __restrict__ var, const float* __restrict__ rsc)
{
    __shared__ float tv[32][33];
    __shared__ float tr[32][33];
    const int tx = threadIdx.x, ty = threadIdx.y;
    const int s0 = blockIdx.x * 32, k0 = blockIdx.y * 32;
    #pragma unroll
    for (int j = 0; j < 4; ++j) {
        int s = s0 + ty + j * 8;
        tv[ty + j * 8][tx] = var[s * D_ + k0 + tx];
        tr[ty + j * 8][tx] = rsc[s * D_ + k0 + tx];
    }
    __syncthreads();
    #pragma unroll
    for (int j = 0; j < 4; ++j) {
        int k = k0 + ty + j * 8;
        g_varT[k * S_ + s0 + tx] = tv[tx][ty + j * 8];
        g_rscT[k * S_ + s0 + tx] = tr[tx][ty + j * 8];
    }
}

// ---------------------------------------------------------------------------
// Kernel B: build duplicated-pair weight banks. grid 576, 256 threads.
// ---------------------------------------------------------------------------
__global__ __launch_bounds__(256)
void k_prepack(const float* __restrict__ teW2, const float* __restrict__ reW2,
               const float* __restrict__ teW3, const float* __restrict__ reW3,
               const float* __restrict__ decW2)
{
    const int idx = blockIdx.x * 256 + threadIdx.x;
    if (idx < 16384) {
        const float* W2 = (idx >> 13) ? reW2 : teW2;
        float w = W2[idx & 8191];
        g_W2d[idx] = pk(w, w);
    } else if (idx < 81920) {
        int j = idx - 16384;
        const float* W3 = (j >> 15) ? reW3 : teW3;
        float w = W3[j & 32767];
        g_W3d[j] = pk(w, w);
    } else if (idx < 147456) {
        int j = idx - 81920;
        float w = decW2[j];
        g_dW2d[j] = pk(w, w);
    }
}

// ---------------------------------------------------------------------------
// Kernel C: SC1 for 8 sources per block. grid 128, 256 threads.
// ---------------------------------------------------------------------------
__global__ __launch_bounds__(256, 3)
void k_preSC1(const float* __restrict__ src_codes,
              const float* __restrict__ decW1, const float* __restrict__ decb1)
{
    const int s0 = blockIdx.x * 8, t = threadIdx.x;
    __shared__ float scs[8][256];
    #pragma unroll
    for (int q = 0; q < 8; ++q)
        scs[q][t] = src_codes[(s0 + q) * 256 + t];
    __syncthreads();

    float acc[8];
    float bb = decb1[t];
    #pragma unroll
    for (int q = 0; q < 8; ++q) acc[q] = bb;
    #pragma unroll 4
    for (int i = 0; i < 256; ++i) {
        float w = decW1[(256 + i) * 256 + t];
        #pragma unroll
        for (int q = 0; q < 8; ++q)
            acc[q] = fmaf(scs[q][i], w, acc[q]);
    }
    #pragma unroll
    for (int q = 0; q < 8; ++q)
        g_SC1[(s0 + q) * 256 + t] = acc[q];
}

// ---------------------------------------------------------------------------
// Kernel 1: PointNet encoders, grid (64, 2, NQ), 256 threads, 3 CTAs/SM.
// ---------------------------------------------------------------------------
#define TP 32

__global__ __launch_bounds__(256, 3)
void k_pointnet(const float* __restrict__ noc,
                const float* __restrict__ teW1, const float* __restrict__ teb1,
                const float* __restrict__ teb2, const float* __restrict__ teb3,
                const float* __restrict__ reW1, const float* __restrict__ reb1,
                const float* __restrict__ reb2, const float* __restrict__ reb3)
{
    const int b = blockIdx.x;
    const int enc = blockIdx.y;
    const int qz = blockIdx.z;
    const float* W1 = enc ? reW1 : teW1; const float* b1 = enc ? reb1 : teb1;
    const float* b2 = enc ? reb2 : teb2; const float* b3 = enc ? reb3 : teb3;
    const u64* W2d = g_W2d + enc * 8192;
    const u64* W3d = g_W3d + enc * 32768;

    __shared__ __align__(16) float X[3][TP];
    __shared__ __align__(16) float H1c[64][36];
    __shared__ __align__(16) float H2c[128][36];
    __shared__ __align__(16) float red[4][256];

    const int t = threadIdx.x;

    const int colB = t & 63, pgB = t >> 6;
    const int c0C = (t & 31) * 4, pgC = t >> 5;
    const int c0D = (t & 63) * 4, pgD = t >> 6;

    const float w10 = W1[colB], w11 = W1[64 + colB], w12 = W1[128 + colB];
    const float bb1 = b1[colB];
    const float4 bb2 = *(const float4*)&b2[c0C];
    const u64 bb2p[4] = { pk(bb2.x, bb2.x), pk(bb2.y, bb2.y),
                          pk(bb2.z, bb2.z), pk(bb2.w, bb2.w) };
    const float b3v[4] = { b3[c0D], b3[c0D+1], b3[c0D+2], b3[c0D+3] };

    float tmax[4] = {0.f, 0.f, 0.f, 0.f};

    for (int tile = 0; tile < 128 / TP; ++tile) {
        __syncthreads();
        if (t < 96) {
            int c = t >> 5, p = t & 31;
            X[c][p] = noc[b * 3072 + c * 1024 + qz * 128 + tile * TP + p];
        }
        __syncthreads();

        // ---- H1: 3 -> 64 ----
        {
            float v[8];
            #pragma unroll
            for (int pp = 0; pp < 8; ++pp) {
                int p = pgB * 8 + pp;
                float h = fmaf(X[0][p], w10, fmaf(X[1][p], w11, fmaf(X[2][p], w12, bb1)));
                v[pp] = fmaxf(h, 0.f);
            }
            #pragma unroll
            for (int q = 0; q < 4; ++q)
                *(u64*)&H1c[colB][pgB * 8 + 2 * q] = pk(v[2*q], v[2*q+1]);
        }
        __syncthreads();

        // ---- H2: 64 -> 128, f32x2, dup weights ----
        {
            u64 acc[2][4];
            #pragma unroll
            for (int q = 0; q < 2; ++q)
                #pragma unroll
                for (int j = 0; j < 4; ++j) acc[q][j] = bb2p[j];
            #pragma unroll 4
            for (int k = 0; k < 64; ++k) {
                ulonglong2 xa = *(const ulonglong2*)&H1c[k][pgC * 4];
                const ulonglong2* wp = (const ulonglong2*)(W2d + k * 128 + c0C);
                ulonglong2 wab = wp[0], wcd = wp[1];
                acc[0][0] = fma2(xa.x, wab.x, acc[0][0]);
                acc[0][1] = fma2(xa.x, wab.y, acc[0][1]);
                acc[0][2] = fma2(xa.x, wcd.x, acc[0][2]);
                acc[0][3] = fma2(xa.x, wcd.y, acc[0][3]);
                acc[1][0] = fma2(xa.y, wab.x, acc[1][0]);
                acc[1][1] = fma2(xa.y, wab.y, acc[1][1]);
                acc[1][2] = fma2(xa.y, wcd.x, acc[1][2]);
                acc[1][3] = fma2(xa.y, wcd.y, acc[1][3]);
            }
            #pragma unroll
            for (int j = 0; j < 4; ++j) {
                #pragma unroll
                for (int q = 0; q < 2; ++q) {
                    float lo, hi; upk(acc[q][j], lo, hi);
                    lo = fmaxf(lo, 0.f); hi = fmaxf(hi, 0.f);
                    *(u64*)&H2c[c0C + j][pgC * 4 + 2 * q] = pk(lo, hi);
                }
            }
        }
        __syncthreads();

        // ---- H3: 128 -> 256, f32x2, dup weights, bias+relu+max ----
        {
            u64 acc[4][4];
            #pragma unroll
            for (int q = 0; q < 4; ++q)
                #pragma unroll
                for (int j = 0; j < 4; ++j) acc[q][j] = 0ull;
            #pragma unroll 2
            for (int k = 0; k < 128; ++k) {
                const ulonglong2* xp = (const ulonglong2*)&H2c[k][pgD * 8];
                ulonglong2 xa = xp[0], xb = xp[1];
                const ulonglong2* wp = (const ulonglong2*)(W3d + k * 256 + c0D);
                ulonglong2 wab = wp[0], wcd = wp[1];
                acc[0][0] = fma2(xa.x, wab.x, acc[0][0]);
                acc[0][1] = fma2(xa.x, wab.y, acc[0][1]);
                acc[0][2] = fma2(xa.x, wcd.x, acc[0][2]);
                acc[0][3] = fma2(xa.x, wcd.y, acc[0][3]);
                acc[1][0] = fma2(xa.y, wab.x, acc[1][0]);
                acc[1][1] = fma2(xa.y, wab.y, acc[1][1]);
                acc[1][2] = fma2(xa.y, wcd.x, acc[1][2]);
                acc[1][3] = fma2(xa.y, wcd.y, acc[1][3]);
                acc[2][0] = fma2(xb.x, wab.x, acc[2][0]);
                acc[2][1] = fma2(xb.x, wab.y, acc[2][1]);
                acc[2][2] = fma2(xb.x, wcd.x, acc[2][2]);
                acc[2][3] = fma2(xb.x, wcd.y, acc[2][3]);
                acc[3][0] = fma2(xb.y, wab.x, acc[3][0]);
                acc[3][1] = fma2(xb.y, wab.y, acc[3][1]);
                acc[3][2] = fma2(xb.y, wcd.x, acc[3][2]);
                acc[3][3] = fma2(xb.y, wcd.y, acc[3][3]);
            }
            #pragma unroll
            for (int q = 0; q < 4; ++q) {
                #pragma unroll
                for (int j = 0; j < 4; ++j) {
                    float lo, hi; upk(acc[q][j], lo, hi);
                    tmax[j] = fmaxf(tmax[j], fmaxf(lo + b3v[j], 0.f));
                    tmax[j] = fmaxf(tmax[j], fmaxf(hi + b3v[j], 0.f));
                }
            }
        }
    }

    #pragma unroll
    for (int j = 0; j < 4; ++j) red[pgD][c0D + j] = tmax[j];
    __syncthreads();
    float m = fmaxf(fmaxf(red[0][t], red[1][t]), fmaxf(red[2][t], red[3][t]));
    g_pool[((qz * 2 + enc) * B_ + b) * D_ + t] = m;
}

// ---------------------------------------------------------------------------
// Kernel D: P1[s][p] = part[s,p] . W1tail. grid 1024, 256 threads.
// ---------------------------------------------------------------------------
__global__ __launch_bounds__(256, 4)
void k_preP1(const float* __restrict__ part_latent, const float* __restrict__ decW1)
{
    const int s = blockIdx.x, t = threadIdx.x;
    __shared__ float part[NPART][32];
    ((float*)part)[t]       = part_latent[s * (NPART * 32) + t];
    ((float*)part)[t + 256] = part_latent[s * (NPART * 32) + t + 256];
    __syncthreads();

    float wt[32];
    #pragma unroll
    for (int i = 0; i < 32; ++i)
        wt[i] = decW1[(512 + i) * 256 + t];
    #pragma unroll 2
    for (int p = 0; p < NPART; ++p) {
        float v = 0.f;
        #pragma unroll
        for (int i = 0; i < 32; ++i)
            v = fmaf(part[p][i], wt[i], v);
        g_P1[(s * NPART + p) * 256 + t] = v;
    }
}

// ---------------------------------------------------------------------------
// Kernel 2: reduce quarters + final fc + T = tgt @ dec_W1[0:256]
// ---------------------------------------------------------------------------
__global__ __launch_bounds__(256, 1)
void k_fc(const float* __restrict__ teWf, const float* __restrict__ tebf,
          const float* __restrict__ reWf, const float* __restrict__ rebf,
          const float* __restrict__ decW1)
{
    const int b = blockIdx.x, t = threadIdx.x;
    __shared__ float ste[256], sre[256], stgt[256];
    float mte = 0.f, mre = 0.f;
    #pragma unroll
    for (int q = 0; q < NQ; ++q) {
        mte = fmaxf(mte, g_pool[((q * 2 + 0) * B_ + b) * D_ + t]);
        mre = fmaxf(mre, g_pool[((q * 2 + 1) * B_ + b) * D_ + t]);
    }
    ste[t] = mte; sre[t] = mre;
    __syncthreads();

    float a = tebf[t], r = rebf[t];
    #pragma unroll 8
    for (int i = 0; i < 256; ++i) {
        a = fmaf(ste[i], teWf[i * 256 + t], a);
        r = fmaf(sre[i], reWf[i * 256 + t], r);
    }
    g_ret[b * D_ + t] = r;
    stgt[t] = a;
    __syncthreads();

    float tv = 0.f;
    #pragma unroll 8
    for (int i = 0; i < 256; ++i)
        tv = fmaf(stgt[i], decW1[i * 256 + t], tv);
    g_T[b * D_ + t] = tv;
}

// ---------------------------------------------------------------------------
// Kernel 3: distances (coalesced, thread-per-4-sources) + exact top-10
// ---------------------------------------------------------------------------
__global__ __launch_bounds__(256, 1)
void k_dist()
{
    const int b = blockIdx.x, t = threadIdx.x;
    __shared__ float rets[256];
    __shared__ float d[1024];
    __shared__ float sval[256];
    __shared__ int   sidx[256];

    rets[t] = g_ret[b * D_ + t];
    __syncthreads();

    const int s4 = 4 * t;
    float a0 = 0.f, a1 = 0.f, a2 = 0.f, a3 = 0.f;
    #pragma unroll 4
    for (int k = 0; k < 256; ++k) {
        float r = rets[k];
        float4 v = *(const float4*)&g_varT[k * S_ + s4];
        float4 c = *(const float4*)&g_rscT[k * S_ + s4];
        float d0 = r - c.x, d1 = r - c.y, d2 = r - c.z, d3 = r - c.w;
        a0 = fmaf(v.x, d0 * d0, a0);
        a1 = fmaf(v.y, d1 * d1, a1);
        a2 = fmaf(v.z, d2 * d2, a2);
        a3 = fmaf(v.w, d3 * d3, a3);
    }
    d[s4] = a0; d[s4 + 1] = a1; d[s4 + 2] = a2; d[s4 + 3] = a3;
    __syncthreads();

    for (int it = 0; it < KRET; ++it) {
        float bv = 1e30f; int bi = S_;
        #pragma unroll
        for (int q = 0; q < 4; ++q) {
            int s = q * 256 + t;
            float v = d[s];
            if (v < bv || (v == bv && s < bi)) { bv = v; bi = s; }
        }
        sval[t] = bv; sidx[t] = bi;
        __syncthreads();
        for (int off = 128; off > 0; off >>= 1) {
            if (t < off) {
                float v2 = sval[t + off]; int i2 = sidx[t + off];
                if (v2 < sval[t] || (v2 == sval[t] && i2 < sidx[t])) {
                    sval[t] = v2; sidx[t] = i2;
                }
            }
            __syncthreads();
        }
        if (t == 0) {
            g_idx[b * KRET + it] = sidx[0];
            d[sidx[0]] = 1e30f;
        }
        __syncthreads();
    }
}

// ---------------------------------------------------------------------------
// Kernel 4: decoder MLP -> params[96] per (b,k). 4 CTAs/SM.
// ---------------------------------------------------------------------------
__global__ __launch_bounds__(256, 4)
void k_decode_mlp(const float* __restrict__ decb2,
                  const float* __restrict__ decW3, const float* __restrict__ decb3,
                  const float* __restrict__ proj,  const float* __restrict__ defp)
{
    const int bk = blockIdx.x;
    const int b = bk / KRET;
    const int t = threadIdx.x;
    const int s = g_idx[bk];

    __shared__ __align__(16) u64 H1p[256][10];
    __shared__ __align__(16) u64 H2p[256][10];
    __shared__ float raw[NPAR];

    // ---- layer 1: H1[p][c] = relu(T[b][c] + SC1[s][c] + P1[s][p][c]) ----
    {
        float base = g_T[b * D_ + t] + g_SC1[s * 256 + t];
        const float* p1 = &g_P1[s * (NPART * 256) + t];
        #pragma unroll
        for (int pr = 0; pr < 8; ++pr) {
            float lo = fmaxf(base + p1[(2 * pr) * 256], 0.f);
            float hi = fmaxf(base + p1[(2 * pr + 1) * 256], 0.f);
            H1p[t][pr] = pk(lo, hi);
        }
    }
    __syncthreads();

    const int c0 = (t & 63) * 4, pg = t >> 6;

    // ---- H2: 256 -> 256, f32x2, dup weights ----
    {
        u64 acc[2][4];
        float4 bb = *(const float4*)&decb2[c0];
        acc[0][0] = acc[1][0] = pk(bb.x, bb.x);
        acc[0][1] = acc[1][1] = pk(bb.y, bb.y);
        acc[0][2] = acc[1][2] = pk(bb.z, bb.z);
        acc[0][3] = acc[1][3] = pk(bb.w, bb.w);
        #pragma unroll 4
        for (int k = 0; k < 256; ++k) {
            ulonglong2 xx = *(const ulonglong2*)&H1p[k][pg * 2];
            const ulonglong2* wp = (const ulonglong2*)(g_dW2d + k * 256 + c0);
            ulonglong2 wab = wp[0], wcd = wp[1];
            acc[0][0] = fma2(xx.x, wab.x, acc[0][0]);
            acc[0][1] = fma2(xx.x, wab.y, acc[0][1]);
            acc[0][2] = fma2(xx.x, wcd.x, acc[0][2]);
            acc[0][3] = fma2(xx.x, wcd.y, acc[0][3]);
            acc[1][0] = fma2(xx.y, wab.x, acc[1][0]);
            acc[1][1] = fma2(xx.y, wab.y, acc[1][1]);
            acc[1][2] = fma2(xx.y, wcd.x, acc[1][2]);
            acc[1][3] = fma2(xx.y, wcd.y, acc[1][3]);
        }
        #pragma unroll
        for (int j = 0; j < 4; ++j) {
            #pragma unroll
            for (int q = 0; q < 2; ++q) {
                float lo, hi; upk(acc[q][j], lo, hi);
                lo = fmaxf(lo, 0.f); hi = fmaxf(hi, 0.f);
                H2p[c0 + j][pg * 2 + q] = pk(lo, hi);
            }
        }
    }
    __syncthreads();

    // ---- raw = H2 @ W3 + b3 ----
    const float* H2f = (const float*)H2p;   // [k][20], part p at H2f[k*20+p]
    if (t < NPAR) {
        const int p = t / 6, o = t % 6;
        float v = decb3[o];
        #pragma unroll 8
        for (int k = 0; k < 256; ++k)
            v = fmaf(H2f[k * 20 + p], decW3[k * 6 + o], v);
        raw[t] = v;
    }
    __syncthreads();

    // ---- params = proj[s] @ raw + def[s] -> g_par ----
    if (t < NPAR) {
        float v = defp[s * NPAR + t];
        const float* pr = proj + (size_t)s * NPAR * NPAR + t * NPAR;
        #pragma unroll 8
        for (int j = 0; j < NPAR; ++j)
            v = fmaf(pr[j], raw[j], v);
        g_par[bk * NPAR + t] = v;
    }
}

// ---------------------------------------------------------------------------
// Kernel 5: deformation pts = mat[s] @ params. grid (640, 6).
// ---------------------------------------------------------------------------
__global__ __launch_bounds__(256)
void k_deform(const float* __restrict__ mat, float* __restrict__ out)
{
    const int bk = blockIdx.x;
    const int t = threadIdx.x;
    const int s = g_idx[bk];
    __shared__ float par[NPAR];
    if (t < NPAR) par[t] = g_par[bk * NPAR + t];
    __syncthreads();

    const int r = blockIdx.y * 256 + t;
    const float* mr = mat + (size_t)s * PSRC3 * NPAR + (size_t)r * NPAR;
    float v = 0.f;
    #pragma unroll
    for (int j4 = 0; j4 < 24; ++j4) {
        float4 m4 = *(const float4*)&mr[j4 * 4];
        v = fmaf(m4.x, par[j4 * 4 + 0], v);
        v = fmaf(m4.y, par[j4 * 4 + 1], v);
        v = fmaf(m4.z, par[j4 * 4 + 2], v);
        v = fmaf(m4.w, par[j4 * 4 + 3], v);
    }
    out[(size_t)bk * PSRC3 + r] = v;
}

// ---------------------------------------------------------------------------
extern "C" void kernel_launch(void* const* d_in, const int* in_sizes, int n_in,
                              void* d_out, int out_size)
{
    const float* noc  = (const float*)d_in[0];
    const float* teW1 = (const float*)d_in[1];  const float* teb1 = (const float*)d_in[2];
    const float* teW2 = (const float*)d_in[3];  const float* teb2 = (const float*)d_in[4];
    const float* teW3 = (const float*)d_in[5];  const float* teb3 = (const float*)d_in[6];
    const float* teWf = (const float*)d_in[7];  const float* tebf = (const float*)d_in[8];
    const float* reW1 = (const float*)d_in[9];  const float* reb1 = (const float*)d_in[10];
    const float* reW2 = (const float*)d_in[11]; const float* reb2 = (const float*)d_in[12];
    const float* reW3 = (const float*)d_in[13]; const float* reb3 = (const float*)d_in[14];
    const float* reWf = (const float*)d_in[15]; const float* rebf = (const float*)d_in[16];
    const float* decW1 = (const float*)d_in[17]; const float* decb1 = (const float*)d_in[18];
    const float* decW2 = (const float*)d_in[19]; const float* decb2 = (const float*)d_in[20];
    const float* decW3 = (const float*)d_in[21]; const float* decb3 = (const float*)d_in[22];
    const float* ret_src = (const float*)d_in[23];
    const float* src_codes = (const float*)d_in[24];
    const float* src_var = (const float*)d_in[25];
    const float* part_latent = (const float*)d_in[26];
    const float* defp = (const float*)d_in[27];
    const float* proj = (const float*)d_in[28];
    const float* mat  = (const float*)d_in[29];
    float* out = (float*)d_out;

    dim3 gt(32, 8);
    dim3 bt(32, 8);
    k_transpose<<<gt, bt>>>(src_var, ret_src);
    k_prepack<<<576, 256>>>(teW2, reW2, teW3, reW3, decW2);
    k_preSC1<<<128, 256>>>(src_codes, decW1, decb1);
    dim3 g1(B_, 2, NQ);
    k_pointnet<<<g1, 256>>>(noc, teW1, teb1, teb2, teb3,
                            reW1, reb1, reb2, reb3);
    k_preP1<<<S_, 256>>>(part_latent, decW1);
    k_fc<<<B_, 256>>>(teWf, tebf, reWf, rebf, decW1);
    k_dist<<<B_, 256>>>();
    k_decode_mlp<<<B_ * KRET, 256>>>(decb2, decW3, decb3, proj, defp);
    dim3 g5(B_ * KRET, 6);
    k_deform<<<g5, 256>>>(mat, out);
}

// round 5
// speedup vs baseline: 1.0000x; 1.0000x over previous
#include <cuda_runtime.h>
#include <cuda_bf16.h>

// ---------------------------------------------------------------------------
// JointRetriveDeformHead — round 4
//  * k_transpose: var/rsc -> [k][s] layout for coalesced distance kernel.
//  * k_prepack: duplicate-pair (f32x2) weight banks for pointnet H2/H3 and
//    decoder H2 (removes per-iter MOV pair-duplication).
//  * k_dist: thread-per-4-sources sequential-k distances (no shuffles),
//    exact top-10 kept.
//  * k_preSC1: 8 sources/block (8x weight reuse); k_preP1 separate.
//  * pointnet/decode inner loops: broadcast LDS.128 activation pairs +
//    LDG.128 duplicated weight pairs.
// ---------------------------------------------------------------------------

#define B_      64
#define S_      1024
#define D_      256
#define KRET    10
#define NPART   16
#define NPAR    96
#define PSRC3   1536
#define NQ      8

__device__ float g_pool[NQ * 2 * B_ * D_];
__device__ float g_ret [B_ * D_];
__device__ float g_T   [B_ * D_];
__device__ int   g_idx [B_ * KRET];
__device__ float g_par [B_ * KRET * NPAR];
__device__ float g_SC1 [S_ * D_];
__device__ float g_P1  [S_ * NPART * D_];
__device__ float g_varT[D_ * S_];            // [k][s]
__device__ float g_rscT[D_ * S_];            // [k][s]

typedef unsigned long long u64;

__device__ u64 g_W2d[2 * 64 * 128];          // dup pairs per encoder
__device__ u64 g_W3d[2 * 128 * 256];
__device__ u64 g_dW2d[256 * 256];

__device__ __forceinline__ u64 pk(float lo, float hi) {
    u64 r; asm("mov.b64 %0,{%1,%2};" : "=l"(r) : "f"(lo), "f"(hi)); return r;
}
__device__ __forceinline__ void upk(u64 v, float& lo, float& hi) {
    asm("mov.b64 {%0,%1},%2;" : "=f"(lo), "=f"(hi) : "l"(v));
}
__device__ __forceinline__ u64 fma2(u64 a, u64 b, u64 c) {
    u64 d; asm("fma.rn.f32x2 %0,%1,%2,%3;" : "=l"(d) : "l"(a), "l"(b), "l"(c)); return d;
}

// ---------------------------------------------------------------------------
// Kernel A: transpose var & rsc to [k][s]. grid (32,8), block (32,8).
// ---------------------------------------------------------------------------
__global__ __launch_bounds__(256)
void k_transpose(const float* __restrict__ var, const float* __restrict__ rsc)
{
    __shared__ float tv[32][33];
    __shared__ float tr[32][33];
    const int tx = threadIdx.x, ty = threadIdx.y;
    const int s0 = blockIdx.x * 32, k0 = blockIdx.y * 32;
    #pragma unroll
    for (int j = 0; j < 4; ++j) {
        int s = s0 + ty + j * 8;
        tv[ty + j * 8][tx] = var[s * D_ + k0 + tx];
        tr[ty + j * 8][tx] = rsc[s * D_ + k0 + tx];
    }
    __syncthreads();
    #pragma unroll
    for (int j = 0; j < 4; ++j) {
        int k = k0 + ty + j * 8;
        g_varT[k * S_ + s0 + tx] = tv[tx][ty + j * 8];
        g_rscT[k * S_ + s0 + tx] = tr[tx][ty + j * 8];
    }
}

// ---------------------------------------------------------------------------
// Kernel B: build duplicated-pair weight banks. grid 576, 256 threads.
// ---------------------------------------------------------------------------
__global__ __launch_bounds__(256)
void k_prepack(const float* __restrict__ teW2, const float* __restrict__ reW2,
               const float* __restrict__ teW3, const float* __restrict__ reW3,
               const float* __restrict__ decW2)
{
    const int idx = blockIdx.x * 256 + threadIdx.x;
    if (idx < 16384) {
        const float* W2 = (idx >> 13) ? reW2 : teW2;
        float w = W2[idx & 8191];
        g_W2d[idx] = pk(w, w);
    } else if (idx < 81920) {
        int j = idx - 16384;
        const float* W3 = (j >> 15) ? reW3 : teW3;
        float w = W3[j & 32767];
        g_W3d[j] = pk(w, w);
    } else if (idx < 147456) {
        int j = idx - 81920;
        float w = decW2[j];
        g_dW2d[j] = pk(w, w);
    }
}

// ---------------------------------------------------------------------------
// Kernel C: SC1 for 8 sources per block. grid 128, 256 threads.
// ---------------------------------------------------------------------------
__global__ __launch_bounds__(256, 3)
void k_preSC1(const float* __restrict__ src_codes,
              const float* __restrict__ decW1, const float* __restrict__ decb1)
{
    const int s0 = blockIdx.x * 8, t = threadIdx.x;
    __shared__ float scs[8][256];
    #pragma unroll
    for (int q = 0; q < 8; ++q)
        scs[q][t] = src_codes[(s0 + q) * 256 + t];
    __syncthreads();

    float acc[8];
    float bb = decb1[t];
    #pragma unroll
    for (int q = 0; q < 8; ++q) acc[q] = bb;
    #pragma unroll 4
    for (int i = 0; i < 256; ++i) {
        float w = decW1[(256 + i) * 256 + t];
        #pragma unroll
        for (int q = 0; q < 8; ++q)
            acc[q] = fmaf(scs[q][i], w, acc[q]);
    }
    #pragma unroll
    for (int q = 0; q < 8; ++q)
        g_SC1[(s0 + q) * 256 + t] = acc[q];
}

// ---------------------------------------------------------------------------
// Kernel 1: PointNet encoders, grid (64, 2, NQ), 256 threads, 3 CTAs/SM.
// ---------------------------------------------------------------------------
#define TP 32

__global__ __launch_bounds__(256, 3)
void k_pointnet(const float* __restrict__ noc,
                const float* __restrict__ teW1, const float* __restrict__ teb1,
                const float* __restrict__ teb2, const float* __restrict__ teb3,
                const float* __restrict__ reW1, const float* __restrict__ reb1,
                const float* __restrict__ reb2, const float* __restrict__ reb3)
{
    const int b = blockIdx.x;
    const int enc = blockIdx.y;
    const int qz = blockIdx.z;
    const float* W1 = enc ? reW1 : teW1; const float* b1 = enc ? reb1 : teb1;
    const float* b2 = enc ? reb2 : teb2; const float* b3 = enc ? reb3 : teb3;
    const u64* W2d = g_W2d + enc * 8192;
    const u64* W3d = g_W3d + enc * 32768;

    __shared__ __align__(16) float X[3][TP];
    __shared__ __align__(16) float H1c[64][36];
    __shared__ __align__(16) float H2c[128][36];
    __shared__ __align__(16) float red[4][256];

    const int t = threadIdx.x;

    const int colB = t & 63, pgB = t >> 6;
    const int c0C = (t & 31) * 4, pgC = t >> 5;
    const int c0D = (t & 63) * 4, pgD = t >> 6;

    const float w10 = W1[colB], w11 = W1[64 + colB], w12 = W1[128 + colB];
    const float bb1 = b1[colB];
    const float4 bb2 = *(const float4*)&b2[c0C];
    const u64 bb2p[4] = { pk(bb2.x, bb2.x), pk(bb2.y, bb2.y),
                          pk(bb2.z, bb2.z), pk(bb2.w, bb2.w) };
    const float b3v[4] = { b3[c0D], b3[c0D+1], b3[c0D+2], b3[c0D+3] };

    float tmax[4] = {0.f, 0.f, 0.f, 0.f};

    for (int tile = 0; tile < 128 / TP; ++tile) {
        __syncthreads();
        if (t < 96) {
            int c = t >> 5, p = t & 31;
            X[c][p] = noc[b * 3072 + c * 1024 + qz * 128 + tile * TP + p];
        }
        __syncthreads();

        // ---- H1: 3 -> 64 ----
        {
            float v[8];
            #pragma unroll
            for (int pp = 0; pp < 8; ++pp) {
                int p = pgB * 8 + pp;
                float h = fmaf(X[0][p], w10, fmaf(X[1][p], w11, fmaf(X[2][p], w12, bb1)));
                v[pp] = fmaxf(h, 0.f);
            }
            #pragma unroll
            for (int q = 0; q < 4; ++q)
                *(u64*)&H1c[colB][pgB * 8 + 2 * q] = pk(v[2*q], v[2*q+1]);
        }
        __syncthreads();

        // ---- H2: 64 -> 128, f32x2, dup weights ----
        {
            u64 acc[2][4];
            #pragma unroll
            for (int q = 0; q < 2; ++q)
                #pragma unroll
                for (int j = 0; j < 4; ++j) acc[q][j] = bb2p[j];
            #pragma unroll 4
            for (int k = 0; k < 64; ++k) {
                ulonglong2 xa = *(const ulonglong2*)&H1c[k][pgC * 4];
                const ulonglong2* wp = (const ulonglong2*)(W2d + k * 128 + c0C);
                ulonglong2 wab = wp[0], wcd = wp[1];
                acc[0][0] = fma2(xa.x, wab.x, acc[0][0]);
                acc[0][1] = fma2(xa.x, wab.y, acc[0][1]);
                acc[0][2] = fma2(xa.x, wcd.x, acc[0][2]);
                acc[0][3] = fma2(xa.x, wcd.y, acc[0][3]);
                acc[1][0] = fma2(xa.y, wab.x, acc[1][0]);
                acc[1][1] = fma2(xa.y, wab.y, acc[1][1]);
                acc[1][2] = fma2(xa.y, wcd.x, acc[1][2]);
                acc[1][3] = fma2(xa.y, wcd.y, acc[1][3]);
            }
            #pragma unroll
            for (int j = 0; j < 4; ++j) {
                #pragma unroll
                for (int q = 0; q < 2; ++q) {
                    float lo, hi; upk(acc[q][j], lo, hi);
                    lo = fmaxf(lo, 0.f); hi = fmaxf(hi, 0.f);
                    *(u64*)&H2c[c0C + j][pgC * 4 + 2 * q] = pk(lo, hi);
                }
            }
        }
        __syncthreads();

        // ---- H3: 128 -> 256, f32x2, dup weights, bias+relu+max ----
        {
            u64 acc[4][4];
            #pragma unroll
            for (int q = 0; q < 4; ++q)
                #pragma unroll
                for (int j = 0; j < 4; ++j) acc[q][j] = 0ull;
            #pragma unroll 2
            for (int k = 0; k < 128; ++k) {
                const ulonglong2* xp = (const ulonglong2*)&H2c[k][pgD * 8];
                ulonglong2 xa = xp[0], xb = xp[1];
                const ulonglong2* wp = (const ulonglong2*)(W3d + k * 256 + c0D);
                ulonglong2 wab = wp[0], wcd = wp[1];
                acc[0][0] = fma2(xa.x, wab.x, acc[0][0]);
                acc[0][1] = fma2(xa.x, wab.y, acc[0][1]);
                acc[0][2] = fma2(xa.x, wcd.x, acc[0][2]);
                acc[0][3] = fma2(xa.x, wcd.y, acc[0][3]);
                acc[1][0] = fma2(xa.y, wab.x, acc[1][0]);
                acc[1][1] = fma2(xa.y, wab.y, acc[1][1]);
                acc[1][2] = fma2(xa.y, wcd.x, acc[1][2]);
                acc[1][3] = fma2(xa.y, wcd.y, acc[1][3]);
                acc[2][0] = fma2(xb.x, wab.x, acc[2][0]);
                acc[2][1] = fma2(xb.x, wab.y, acc[2][1]);
                acc[2][2] = fma2(xb.x, wcd.x, acc[2][2]);
                acc[2][3] = fma2(xb.x, wcd.y, acc[2][3]);
                acc[3][0] = fma2(xb.y, wab.x, acc[3][0]);
                acc[3][1] = fma2(xb.y, wab.y, acc[3][1]);
                acc[3][2] = fma2(xb.y, wcd.x, acc[3][2]);
                acc[3][3] = fma2(xb.y, wcd.y, acc[3][3]);
            }
            #pragma unroll
            for (int q = 0; q < 4; ++q) {
                #pragma unroll
                for (int j = 0; j < 4; ++j) {
                    float lo, hi; upk(acc[q][j], lo, hi);
                    tmax[j] = fmaxf(tmax[j], fmaxf(lo + b3v[j], 0.f));
                    tmax[j] = fmaxf(tmax[j], fmaxf(hi + b3v[j], 0.f));
                }
            }
        }
    }

    #pragma unroll
    for (int j = 0; j < 4; ++j) red[pgD][c0D + j] = tmax[j];
    __syncthreads();
    float m = fmaxf(fmaxf(red[0][t], red[1][t]), fmaxf(red[2][t], red[3][t]));
    g_pool[((qz * 2 + enc) * B_ + b) * D_ + t] = m;
}

// ---------------------------------------------------------------------------
// Kernel D: P1[s][p] = part[s,p] . W1tail. grid 1024, 256 threads.
// ---------------------------------------------------------------------------
__global__ __launch_bounds__(256, 4)
void k_preP1(const float* __restrict__ part_latent, const float* __restrict__ decW1)
{
    const int s = blockIdx.x, t = threadIdx.x;
    __shared__ float part[NPART][32];
    ((float*)part)[t]       = part_latent[s * (NPART * 32) + t];
    ((float*)part)[t + 256] = part_latent[s * (NPART * 32) + t + 256];
    __syncthreads();

    float wt[32];
    #pragma unroll
    for (int i = 0; i < 32; ++i)
        wt[i] = decW1[(512 + i) * 256 + t];
    #pragma unroll 2
    for (int p = 0; p < NPART; ++p) {
        float v = 0.f;
        #pragma unroll
        for (int i = 0; i < 32; ++i)
            v = fmaf(part[p][i], wt[i], v);
        g_P1[(s * NPART + p) * 256 + t] = v;
    }
}

// ---------------------------------------------------------------------------
// Kernel 2: reduce quarters + final fc + T = tgt @ dec_W1[0:256]
// ---------------------------------------------------------------------------
__global__ __launch_bounds__(256, 1)
void k_fc(const float* __restrict__ teWf, const float* __restrict__ tebf,
          const float* __restrict__ reWf, const float* __restrict__ rebf,
          const float* __restrict__ decW1)
{
    const int b = blockIdx.x, t = threadIdx.x;
    __shared__ float ste[256], sre[256], stgt[256];
    float mte = 0.f, mre = 0.f;
    #pragma unroll
    for (int q = 0; q < NQ; ++q) {
        mte = fmaxf(mte, g_pool[((q * 2 + 0) * B_ + b) * D_ + t]);
        mre = fmaxf(mre, g_pool[((q * 2 + 1) * B_ + b) * D_ + t]);
    }
    ste[t] = mte; sre[t] = mre;
    __syncthreads();

    float a = tebf[t], r = rebf[t];
    #pragma unroll 8
    for (int i = 0; i < 256; ++i) {
        a = fmaf(ste[i], teWf[i * 256 + t], a);
        r = fmaf(sre[i], reWf[i * 256 + t], r);
    }
    g_ret[b * D_ + t] = r;
    stgt[t] = a;
    __syncthreads();

    float tv = 0.f;
    #pragma unroll 8
    for (int i = 0; i < 256; ++i)
        tv = fmaf(stgt[i], decW1[i * 256 + t], tv);
    g_T[b * D_ + t] = tv;
}

// ---------------------------------------------------------------------------
// Kernel 3: distances (coalesced, thread-per-4-sources) + exact top-10
// ---------------------------------------------------------------------------
__global__ __launch_bounds__(256, 1)
void k_dist()
{
    const int b = blockIdx.x, t = threadIdx.x;
    __shared__ float rets[256];
    __shared__ float d[1024];
    __shared__ float sval[256];
    __shared__ int   sidx[256];

    rets[t] = g_ret[b * D_ + t];
    __syncthreads();

    const int s4 = 4 * t;
    float a0 = 0.f, a1 = 0.f, a2 = 0.f, a3 = 0.f;
    #pragma unroll 4
    for (int k = 0; k < 256; ++k) {
        float r = rets[k];
        float4 v = *(const float4*)&g_varT[k * S_ + s4];
        float4 c = *(const float4*)&g_rscT[k * S_ + s4];
        float d0 = r - c.x, d1 = r - c.y, d2 = r - c.z, d3 = r - c.w;
        a0 = fmaf(v.x, d0 * d0, a0);
        a1 = fmaf(v.y, d1 * d1, a1);
        a2 = fmaf(v.z, d2 * d2, a2);
        a3 = fmaf(v.w, d3 * d3, a3);
    }
    d[s4] = a0; d[s4 + 1] = a1; d[s4 + 2] = a2; d[s4 + 3] = a3;
    __syncthreads();

    for (int it = 0; it < KRET; ++it) {
        float bv = 1e30f; int bi = S_;
        #pragma unroll
        for (int q = 0; q < 4; ++q) {
            int s = q * 256 + t;
            float v = d[s];
            if (v < bv || (v == bv && s < bi)) { bv = v; bi = s; }
        }
        sval[t] = bv; sidx[t] = bi;
        __syncthreads();
        for (int off = 128; off > 0; off >>= 1) {
            if (t < off) {
                float v2 = sval[t + off]; int i2 = sidx[t + off];
                if (v2 < sval[t] || (v2 == sval[t] && i2 < sidx[t])) {
                    sval[t] = v2; sidx[t] = i2;
                }
            }
            __syncthreads();
        }
        if (t == 0) {
            g_idx[b * KRET + it] = sidx[0];
            d[sidx[0]] = 1e30f;
        }
        __syncthreads();
    }
}

// ---------------------------------------------------------------------------
// Kernel 4: decoder MLP -> params[96] per (b,k). 4 CTAs/SM.
// ---------------------------------------------------------------------------
__global__ __launch_bounds__(256, 4)
void k_decode_mlp(const float* __restrict__ decb2,
                  const float* __restrict__ decW3, const float* __restrict__ decb3,
                  const float* __restrict__ proj,  const float* __restrict__ defp)
{
    const int bk = blockIdx.x;
    const int b = bk / KRET;
    const int t = threadIdx.x;
    const int s = g_idx[bk];

    __shared__ __align__(16) u64 H1p[256][10];
    __shared__ __align__(16) u64 H2p[256][10];
    __shared__ float raw[NPAR];

    // ---- layer 1: H1[p][c] = relu(T[b][c] + SC1[s][c] + P1[s][p][c]) ----
    {
        float base = g_T[b * D_ + t] + g_SC1[s * 256 + t];
        const float* p1 = &g_P1[s * (NPART * 256) + t];
        #pragma unroll
        for (int pr = 0; pr < 8; ++pr) {
            float lo = fmaxf(base + p1[(2 * pr) * 256], 0.f);
            float hi = fmaxf(base + p1[(2 * pr + 1) * 256], 0.f);
            H1p[t][pr] = pk(lo, hi);
        }
    }
    __syncthreads();

    const int c0 = (t & 63) * 4, pg = t >> 6;

    // ---- H2: 256 -> 256, f32x2, dup weights ----
    {
        u64 acc[2][4];
        float4 bb = *(const float4*)&decb2[c0];
        acc[0][0] = acc[1][0] = pk(bb.x, bb.x);
        acc[0][1] = acc[1][1] = pk(bb.y, bb.y);
        acc[0][2] = acc[1][2] = pk(bb.z, bb.z);
        acc[0][3] = acc[1][3] = pk(bb.w, bb.w);
        #pragma unroll 4
        for (int k = 0; k < 256; ++k) {
            ulonglong2 xx = *(const ulonglong2*)&H1p[k][pg * 2];
            const ulonglong2* wp = (const ulonglong2*)(g_dW2d + k * 256 + c0);
            ulonglong2 wab = wp[0], wcd = wp[1];
            acc[0][0] = fma2(xx.x, wab.x, acc[0][0]);
            acc[0][1] = fma2(xx.x, wab.y, acc[0][1]);
            acc[0][2] = fma2(xx.x, wcd.x, acc[0][2]);
            acc[0][3] = fma2(xx.x, wcd.y, acc[0][3]);
            acc[1][0] = fma2(xx.y, wab.x, acc[1][0]);
            acc[1][1] = fma2(xx.y, wab.y, acc[1][1]);
            acc[1][2] = fma2(xx.y, wcd.x, acc[1][2]);
            acc[1][3] = fma2(xx.y, wcd.y, acc[1][3]);
        }
        #pragma unroll
        for (int j = 0; j < 4; ++j) {
            #pragma unroll
            for (int q = 0; q < 2; ++q) {
                float lo, hi; upk(acc[q][j], lo, hi);
                lo = fmaxf(lo, 0.f); hi = fmaxf(hi, 0.f);
                H2p[c0 + j][pg * 2 + q] = pk(lo, hi);
            }
        }
    }
    __syncthreads();

    // ---- raw = H2 @ W3 + b3 ----
    const float* H2f = (const float*)H2p;   // [k][20], part p at H2f[k*20+p]
    if (t < NPAR) {
        const int p = t / 6, o = t % 6;
        float v = decb3[o];
        #pragma unroll 8
        for (int k = 0; k < 256; ++k)
            v = fmaf(H2f[k * 20 + p], decW3[k * 6 + o], v);
        raw[t] = v;
    }
    __syncthreads();

    // ---- params = proj[s] @ raw + def[s] -> g_par ----
    if (t < NPAR) {
        float v = defp[s * NPAR + t];
        const float* pr = proj + (size_t)s * NPAR * NPAR + t * NPAR;
        #pragma unroll 8
        for (int j = 0; j < NPAR; ++j)
            v = fmaf(pr[j], raw[j], v);
        g_par[bk * NPAR + t] = v;
    }
}

// ---------------------------------------------------------------------------
// Kernel 5: deformation pts = mat[s] @ params. grid (640, 6).
// ---------------------------------------------------------------------------
__global__ __launch_bounds__(256)
void k_deform(const float* __restrict__ mat, float* __restrict__ out)
{
    const int bk = blockIdx.x;
    const int t = threadIdx.x;
    const int s = g_idx[bk];
    __shared__ float par[NPAR];
    if (t < NPAR) par[t] = g_par[bk * NPAR + t];
    __syncthreads();

    const int r = blockIdx.y * 256 + t;
    const float* mr = mat + (size_t)s * PSRC3 * NPAR + (size_t)r * NPAR;
    float v = 0.f;
    #pragma unroll
    for (int j4 = 0; j4 < 24; ++j4) {
        float4 m4 = *(const float4*)&mr[j4 * 4];
        v = fmaf(m4.x, par[j4 * 4 + 0], v);
        v = fmaf(m4.y, par[j4 * 4 + 1], v);
        v = fmaf(m4.z, par[j4 * 4 + 2], v);
        v = fmaf(m4.w, par[j4 * 4 + 3], v);
    }
    out[(size_t)bk * PSRC3 + r] = v;
}

// ---------------------------------------------------------------------------
extern "C" void kernel_launch(void* const* d_in, const int* in_sizes, int n_in,
                              void* d_out, int out_size)
{
    const float* noc  = (const float*)d_in[0];
    const float* teW1 = (const float*)d_in[1];  const float* teb1 = (const float*)d_in[2];
    const float* teW2 = (const float*)d_in[3];  const float* teb2 = (const float*)d_in[4];
    const float* teW3 = (const float*)d_in[5];  const float* teb3 = (const float*)d_in[6];
    const float* teWf = (const float*)d_in[7];  const float* tebf = (const float*)d_in[8];
    const float* reW1 = (const float*)d_in[9];  const float* reb1 = (const float*)d_in[10];
    const float* reW2 = (const float*)d_in[11]; const float* reb2 = (const float*)d_in[12];
    const float* reW3 = (const float*)d_in[13]; const float* reb3 = (const float*)d_in[14];
    const float* reWf = (const float*)d_in[15]; const float* rebf = (const float*)d_in[16];
    const float* decW1 = (const float*)d_in[17]; const float* decb1 = (const float*)d_in[18];
    const float* decW2 = (const float*)d_in[19]; const float* decb2 = (const float*)d_in[20];
    const float* decW3 = (const float*)d_in[21]; const float* decb3 = (const float*)d_in[22];
    const float* ret_src = (const float*)d_in[23];
    const float* src_codes = (const float*)d_in[24];
    const float* src_var = (const float*)d_in[25];
    const float* part_latent = (const float*)d_in[26];
    const float* defp = (const float*)d_in[27];
    const float* proj = (const float*)d_in[28];
    const float* mat  = (const float*)d_in[29];
    float* out = (float*)d_out;

    dim3 gt(32, 8);
    dim3 bt(32, 8);
    k_transpose<<<gt, bt>>>(src_var, ret_src);
    k_prepack<<<576, 256>>>(teW2, reW2, teW3, reW3, decW2);
    k_preSC1<<<128, 256>>>(src_codes, decW1, decb1);
    dim3 g1(B_, 2, NQ);
    k_pointnet<<<g1, 256>>>(noc, teW1, teb1, teb2, teb3,
                            reW1, reb1, reb2, reb3);
    k_preP1<<<S_, 256>>>(part_latent, decW1);
    k_fc<<<B_, 256>>>(teWf, tebf, reWf, rebf, decW1);
    k_dist<<<B_, 256>>>();
    k_decode_mlp<<<B_ * KRET, 256>>>(decb2, decW3, decb3, proj, defp);
    dim3 g5(B_ * KRET, 6);
    k_deform<<<g5, 256>>>(mat, out);
}

// round 6
// speedup vs baseline: 1.6052x; 1.6051x over previous
#include <cuda_runtime.h>
#include <cuda_bf16.h>

// ---------------------------------------------------------------------------
// JointRetriveDeformHead — round 5
//  * REVERT round-4 dup-weight banks (L1-bandwidth regression: 32B/iter
//    weight loads thrashed L1). Back to float4 weights + inline pair-dup.
//  * KEEP round-4 k_transpose + coalesced k_dist (87 -> ~15 us win).
//  * KEEP split k_preSC1 (8 src/block) + k_preP1.
//  * smem pads 36 / H1p[10]: activation pairs load as LDS.128.
// ---------------------------------------------------------------------------

#define B_      64
#define S_      1024
#define D_      256
#define KRET    10
#define NPART   16
#define NPAR    96
#define PSRC3   1536
#define NQ      8

__device__ float g_pool[NQ * 2 * B_ * D_];
__device__ float g_ret [B_ * D_];
__device__ float g_T   [B_ * D_];
__device__ int   g_idx [B_ * KRET];
__device__ float g_par [B_ * KRET * NPAR];
__device__ float g_SC1 [S_ * D_];
__device__ float g_P1  [S_ * NPART * D_];
__device__ float g_varT[D_ * S_];
__device__ float g_rscT[D_ * S_];

typedef unsigned long long u64;

__device__ __forceinline__ u64 pk(float lo, float hi) {
    u64 r; asm("mov.b64 %0,{%1,%2};" : "=l"(r) : "f"(lo), "f"(hi)); return r;
}
__device__ __forceinline__ void upk(u64 v, float& lo, float& hi) {
    asm("mov.b64 {%0,%1},%2;" : "=f"(lo), "=f"(hi) : "l"(v));
}
__device__ __forceinline__ u64 fma2(u64 a, u64 b, u64 c) {
    u64 d; asm("fma.rn.f32x2 %0,%1,%2,%3;" : "=l"(d) : "l"(a), "l"(b), "l"(c)); return d;
}

// ---------------------------------------------------------------------------
// Kernel A: transpose var & rsc to [k][s]. grid (32,8), block (32,8).
// ---------------------------------------------------------------------------
__global__ __launch_bounds__(256)
void k_transpose(const float* __restrict__ var, const float* __restrict__ rsc)
{
    __shared__ float tv[32][33];
    __shared__ float tr[32][33];
    const int tx = threadIdx.x, ty = threadIdx.y;
    const int s0 = blockIdx.x * 32, k0 = blockIdx.y * 32;
    #pragma unroll
    for (int j = 0; j < 4; ++j) {
        int s = s0 + ty + j * 8;
        tv[ty + j * 8][tx] = var[s * D_ + k0 + tx];
        tr[ty + j * 8][tx] = rsc[s * D_ + k0 + tx];
    }
    __syncthreads();
    #pragma unroll
    for (int j = 0; j < 4; ++j) {
        int k = k0 + ty + j * 8;
        g_varT[k * S_ + s0 + tx] = tv[tx][ty + j * 8];
        g_rscT[k * S_ + s0 + tx] = tr[tx][ty + j * 8];
    }
}

// ---------------------------------------------------------------------------
// Kernel C: SC1 for 8 sources per block. grid 128, 256 threads.
// ---------------------------------------------------------------------------
__global__ __launch_bounds__(256, 3)
void k_preSC1(const float* __restrict__ src_codes,
              const float* __restrict__ decW1, const float* __restrict__ decb1)
{
    const int s0 = blockIdx.x * 8, t = threadIdx.x;
    __shared__ float scs[8][256];
    #pragma unroll
    for (int q = 0; q < 8; ++q)
        scs[q][t] = src_codes[(s0 + q) * 256 + t];
    __syncthreads();

    float acc[8];
    float bb = decb1[t];
    #pragma unroll
    for (int q = 0; q < 8; ++q) acc[q] = bb;
    #pragma unroll 4
    for (int i = 0; i < 256; ++i) {
        float w = decW1[(256 + i) * 256 + t];
        #pragma unroll
        for (int q = 0; q < 8; ++q)
            acc[q] = fmaf(scs[q][i], w, acc[q]);
    }
    #pragma unroll
    for (int q = 0; q < 8; ++q)
        g_SC1[(s0 + q) * 256 + t] = acc[q];
}

// ---------------------------------------------------------------------------
// Kernel D: P1[s][p] = part[s,p] . W1tail. grid 1024, 256 threads.
// ---------------------------------------------------------------------------
__global__ __launch_bounds__(256, 4)
void k_preP1(const float* __restrict__ part_latent, const float* __restrict__ decW1)
{
    const int s = blockIdx.x, t = threadIdx.x;
    __shared__ float part[NPART][32];
    ((float*)part)[t]       = part_latent[s * (NPART * 32) + t];
    ((float*)part)[t + 256] = part_latent[s * (NPART * 32) + t + 256];
    __syncthreads();

    float wt[32];
    #pragma unroll
    for (int i = 0; i < 32; ++i)
        wt[i] = decW1[(512 + i) * 256 + t];
    #pragma unroll 2
    for (int p = 0; p < NPART; ++p) {
        float v = 0.f;
        #pragma unroll
        for (int i = 0; i < 32; ++i)
            v = fmaf(part[p][i], wt[i], v);
        g_P1[(s * NPART + p) * 256 + t] = v;
    }
}

// ---------------------------------------------------------------------------
// Kernel 1: PointNet encoders, grid (64, 2, NQ), 256 threads, 3 CTAs/SM.
// float4 weight loads (16B/iter) + inline pair duplication (L1-friendly).
// ---------------------------------------------------------------------------
#define TP 32

__global__ __launch_bounds__(256, 3)
void k_pointnet(const float* __restrict__ noc,
                const float* __restrict__ teW1, const float* __restrict__ teb1,
                const float* __restrict__ teW2, const float* __restrict__ teb2,
                const float* __restrict__ teW3, const float* __restrict__ teb3,
                const float* __restrict__ reW1, const float* __restrict__ reb1,
                const float* __restrict__ reW2, const float* __restrict__ reb2,
                const float* __restrict__ reW3, const float* __restrict__ reb3)
{
    const int b = blockIdx.x;
    const int enc = blockIdx.y;
    const int qz = blockIdx.z;
    const float* W1 = enc ? reW1 : teW1; const float* b1 = enc ? reb1 : teb1;
    const float* W2 = enc ? reW2 : teW2; const float* b2 = enc ? reb2 : teb2;
    const float* W3 = enc ? reW3 : teW3; const float* b3 = enc ? reb3 : teb3;

    __shared__ __align__(16) float X[3][TP];
    __shared__ __align__(16) float H1c[64][36];
    __shared__ __align__(16) float H2c[128][36];
    __shared__ __align__(16) float red[4][256];

    const int t = threadIdx.x;

    const int colB = t & 63, pgB = t >> 6;
    const int c0C = (t & 31) * 4, pgC = t >> 5;
    const int c0D = (t & 63) * 4, pgD = t >> 6;

    const float w10 = W1[colB], w11 = W1[64 + colB], w12 = W1[128 + colB];
    const float bb1 = b1[colB];
    const float4 bb2 = *(const float4*)&b2[c0C];
    const u64 bb2p[4] = { pk(bb2.x, bb2.x), pk(bb2.y, bb2.y),
                          pk(bb2.z, bb2.z), pk(bb2.w, bb2.w) };
    const float b3v[4] = { b3[c0D], b3[c0D+1], b3[c0D+2], b3[c0D+3] };

    float tmax[4] = {0.f, 0.f, 0.f, 0.f};

    for (int tile = 0; tile < 128 / TP; ++tile) {
        __syncthreads();
        if (t < 96) {
            int c = t >> 5, p = t & 31;
            X[c][p] = noc[b * 3072 + c * 1024 + qz * 128 + tile * TP + p];
        }
        __syncthreads();

        // ---- H1: 3 -> 64 ----
        {
            float v[8];
            #pragma unroll
            for (int pp = 0; pp < 8; ++pp) {
                int p = pgB * 8 + pp;
                float h = fmaf(X[0][p], w10, fmaf(X[1][p], w11, fmaf(X[2][p], w12, bb1)));
                v[pp] = fmaxf(h, 0.f);
            }
            #pragma unroll
            for (int q = 0; q < 4; ++q)
                *(u64*)&H1c[colB][pgB * 8 + 2 * q] = pk(v[2*q], v[2*q+1]);
        }
        __syncthreads();

        // ---- H2: 64 -> 128, f32x2 ----
        {
            u64 acc[2][4];
            #pragma unroll
            for (int q = 0; q < 2; ++q)
                #pragma unroll
                for (int j = 0; j < 4; ++j) acc[q][j] = bb2p[j];
            #pragma unroll 4
            for (int k = 0; k < 64; ++k) {
                ulonglong2 xa = *(const ulonglong2*)&H1c[k][pgC * 4];
                float4 w = *(const float4*)&W2[k * 128 + c0C];
                u64 wp0 = pk(w.x, w.x), wp1 = pk(w.y, w.y);
                u64 wp2 = pk(w.z, w.z), wp3 = pk(w.w, w.w);
                acc[0][0] = fma2(xa.x, wp0, acc[0][0]);
                acc[0][1] = fma2(xa.x, wp1, acc[0][1]);
                acc[0][2] = fma2(xa.x, wp2, acc[0][2]);
                acc[0][3] = fma2(xa.x, wp3, acc[0][3]);
                acc[1][0] = fma2(xa.y, wp0, acc[1][0]);
                acc[1][1] = fma2(xa.y, wp1, acc[1][1]);
                acc[1][2] = fma2(xa.y, wp2, acc[1][2]);
                acc[1][3] = fma2(xa.y, wp3, acc[1][3]);
            }
            #pragma unroll
            for (int j = 0; j < 4; ++j) {
                #pragma unroll
                for (int q = 0; q < 2; ++q) {
                    float lo, hi; upk(acc[q][j], lo, hi);
                    lo = fmaxf(lo, 0.f); hi = fmaxf(hi, 0.f);
                    *(u64*)&H2c[c0C + j][pgC * 4 + 2 * q] = pk(lo, hi);
                }
            }
        }
        __syncthreads();

        // ---- H3: 128 -> 256, f32x2, bias+relu+running max ----
        {
            u64 acc[4][4];
            #pragma unroll
            for (int q = 0; q < 4; ++q)
                #pragma unroll
                for (int j = 0; j < 4; ++j) acc[q][j] = 0ull;
            #pragma unroll 2
            for (int k = 0; k < 128; ++k) {
                const ulonglong2* xp = (const ulonglong2*)&H2c[k][pgD * 8];
                ulonglong2 xa = xp[0], xb = xp[1];
                float4 w = *(const float4*)&W3[k * 256 + c0D];
                u64 wp0 = pk(w.x, w.x), wp1 = pk(w.y, w.y);
                u64 wp2 = pk(w.z, w.z), wp3 = pk(w.w, w.w);
                acc[0][0] = fma2(xa.x, wp0, acc[0][0]);
                acc[0][1] = fma2(xa.x, wp1, acc[0][1]);
                acc[0][2] = fma2(xa.x, wp2, acc[0][2]);
                acc[0][3] = fma2(xa.x, wp3, acc[0][3]);
                acc[1][0] = fma2(xa.y, wp0, acc[1][0]);
                acc[1][1] = fma2(xa.y, wp1, acc[1][1]);
                acc[1][2] = fma2(xa.y, wp2, acc[1][2]);
                acc[1][3] = fma2(xa.y, wp3, acc[1][3]);
                acc[2][0] = fma2(xb.x, wp0, acc[2][0]);
                acc[2][1] = fma2(xb.x, wp1, acc[2][1]);
                acc[2][2] = fma2(xb.x, wp2, acc[2][2]);
                acc[2][3] = fma2(xb.x, wp3, acc[2][3]);
                acc[3][0] = fma2(xb.y, wp0, acc[3][0]);
                acc[3][1] = fma2(xb.y, wp1, acc[3][1]);
                acc[3][2] = fma2(xb.y, wp2, acc[3][2]);
                acc[3][3] = fma2(xb.y, wp3, acc[3][3]);
            }
            #pragma unroll
            for (int q = 0; q < 4; ++q) {
                #pragma unroll
                for (int j = 0; j < 4; ++j) {
                    float lo, hi; upk(acc[q][j], lo, hi);
                    tmax[j] = fmaxf(tmax[j], fmaxf(lo + b3v[j], 0.f));
                    tmax[j] = fmaxf(tmax[j], fmaxf(hi + b3v[j], 0.f));
                }
            }
        }
    }

    #pragma unroll
    for (int j = 0; j < 4; ++j) red[pgD][c0D + j] = tmax[j];
    __syncthreads();
    float m = fmaxf(fmaxf(red[0][t], red[1][t]), fmaxf(red[2][t], red[3][t]));
    g_pool[((qz * 2 + enc) * B_ + b) * D_ + t] = m;
}

// ---------------------------------------------------------------------------
// Kernel 2: reduce quarters + final fc + T = tgt @ dec_W1[0:256]
// ---------------------------------------------------------------------------
__global__ __launch_bounds__(256, 1)
void k_fc(const float* __restrict__ teWf, const float* __restrict__ tebf,
          const float* __restrict__ reWf, const float* __restrict__ rebf,
          const float* __restrict__ decW1)
{
    const int b = blockIdx.x, t = threadIdx.x;
    __shared__ float ste[256], sre[256], stgt[256];
    float mte = 0.f, mre = 0.f;
    #pragma unroll
    for (int q = 0; q < NQ; ++q) {
        mte = fmaxf(mte, g_pool[((q * 2 + 0) * B_ + b) * D_ + t]);
        mre = fmaxf(mre, g_pool[((q * 2 + 1) * B_ + b) * D_ + t]);
    }
    ste[t] = mte; sre[t] = mre;
    __syncthreads();

    float a = tebf[t], r = rebf[t];
    #pragma unroll 8
    for (int i = 0; i < 256; ++i) {
        a = fmaf(ste[i], teWf[i * 256 + t], a);
        r = fmaf(sre[i], reWf[i * 256 + t], r);
    }
    g_ret[b * D_ + t] = r;
    stgt[t] = a;
    __syncthreads();

    float tv = 0.f;
    #pragma unroll 8
    for (int i = 0; i < 256; ++i)
        tv = fmaf(stgt[i], decW1[i * 256 + t], tv);
    g_T[b * D_ + t] = tv;
}

// ---------------------------------------------------------------------------
// Kernel 3: distances (coalesced, thread-per-4-sources) + exact top-10
// ---------------------------------------------------------------------------
__global__ __launch_bounds__(256, 1)
void k_dist()
{
    const int b = blockIdx.x, t = threadIdx.x;
    __shared__ float rets[256];
    __shared__ float d[1024];
    __shared__ float sval[256];
    __shared__ int   sidx[256];

    rets[t] = g_ret[b * D_ + t];
    __syncthreads();

    const int s4 = 4 * t;
    float a0 = 0.f, a1 = 0.f, a2 = 0.f, a3 = 0.f;
    #pragma unroll 4
    for (int k = 0; k < 256; ++k) {
        float r = rets[k];
        float4 v = *(const float4*)&g_varT[k * S_ + s4];
        float4 c = *(const float4*)&g_rscT[k * S_ + s4];
        float d0 = r - c.x, d1 = r - c.y, d2 = r - c.z, d3 = r - c.w;
        a0 = fmaf(v.x, d0 * d0, a0);
        a1 = fmaf(v.y, d1 * d1, a1);
        a2 = fmaf(v.z, d2 * d2, a2);
        a3 = fmaf(v.w, d3 * d3, a3);
    }
    d[s4] = a0; d[s4 + 1] = a1; d[s4 + 2] = a2; d[s4 + 3] = a3;
    __syncthreads();

    for (int it = 0; it < KRET; ++it) {
        float bv = 1e30f; int bi = S_;
        #pragma unroll
        for (int q = 0; q < 4; ++q) {
            int s = q * 256 + t;
            float v = d[s];
            if (v < bv || (v == bv && s < bi)) { bv = v; bi = s; }
        }
        sval[t] = bv; sidx[t] = bi;
        __syncthreads();
        for (int off = 128; off > 0; off >>= 1) {
            if (t < off) {
                float v2 = sval[t + off]; int i2 = sidx[t + off];
                if (v2 < sval[t] || (v2 == sval[t] && i2 < sidx[t])) {
                    sval[t] = v2; sidx[t] = i2;
                }
            }
            __syncthreads();
        }
        if (t == 0) {
            g_idx[b * KRET + it] = sidx[0];
            d[sidx[0]] = 1e30f;
        }
        __syncthreads();
    }
}

// ---------------------------------------------------------------------------
// Kernel 4: decoder MLP -> params[96] per (b,k). 4 CTAs/SM.
// ---------------------------------------------------------------------------
__global__ __launch_bounds__(256, 4)
void k_decode_mlp(const float* __restrict__ decW2, const float* __restrict__ decb2,
                  const float* __restrict__ decW3, const float* __restrict__ decb3,
                  const float* __restrict__ proj,  const float* __restrict__ defp)
{
    const int bk = blockIdx.x;
    const int b = bk / KRET;
    const int t = threadIdx.x;
    const int s = g_idx[bk];

    __shared__ __align__(16) u64 H1p[256][10];
    __shared__ __align__(16) u64 H2p[256][10];
    __shared__ float raw[NPAR];

    // ---- layer 1: H1[p][c] = relu(T[b][c] + SC1[s][c] + P1[s][p][c]) ----
    {
        float base = g_T[b * D_ + t] + g_SC1[s * 256 + t];
        const float* p1 = &g_P1[s * (NPART * 256) + t];
        #pragma unroll
        for (int pr = 0; pr < 8; ++pr) {
            float lo = fmaxf(base + p1[(2 * pr) * 256], 0.f);
            float hi = fmaxf(base + p1[(2 * pr + 1) * 256], 0.f);
            H1p[t][pr] = pk(lo, hi);
        }
    }
    __syncthreads();

    const int c0 = (t & 63) * 4, pg = t >> 6;

    // ---- H2: 256 -> 256, f32x2 ----
    {
        u64 acc[2][4];
        float4 bb = *(const float4*)&decb2[c0];
        acc[0][0] = acc[1][0] = pk(bb.x, bb.x);
        acc[0][1] = acc[1][1] = pk(bb.y, bb.y);
        acc[0][2] = acc[1][2] = pk(bb.z, bb.z);
        acc[0][3] = acc[1][3] = pk(bb.w, bb.w);
        #pragma unroll 4
        for (int k = 0; k < 256; ++k) {
            ulonglong2 xx = *(const ulonglong2*)&H1p[k][pg * 2];
            float4 w = *(const float4*)&decW2[k * 256 + c0];
            u64 wp0 = pk(w.x, w.x), wp1 = pk(w.y, w.y);
            u64 wp2 = pk(w.z, w.z), wp3 = pk(w.w, w.w);
            acc[0][0] = fma2(xx.x, wp0, acc[0][0]);
            acc[0][1] = fma2(xx.x, wp1, acc[0][1]);
            acc[0][2] = fma2(xx.x, wp2, acc[0][2]);
            acc[0][3] = fma2(xx.x, wp3, acc[0][3]);
            acc[1][0] = fma2(xx.y, wp0, acc[1][0]);
            acc[1][1] = fma2(xx.y, wp1, acc[1][1]);
            acc[1][2] = fma2(xx.y, wp2, acc[1][2]);
            acc[1][3] = fma2(xx.y, wp3, acc[1][3]);
        }
        #pragma unroll
        for (int j = 0; j < 4; ++j) {
            #pragma unroll
            for (int q = 0; q < 2; ++q) {
                float lo, hi; upk(acc[q][j], lo, hi);
                lo = fmaxf(lo, 0.f); hi = fmaxf(hi, 0.f);
                H2p[c0 + j][pg * 2 + q] = pk(lo, hi);
            }
        }
    }
    __syncthreads();

    // ---- raw = H2 @ W3 + b3 ----
    const float* H2f = (const float*)H2p;   // [k][20], part p at H2f[k*20+p]
    if (t < NPAR) {
        const int p = t / 6, o = t % 6;
        float v = decb3[o];
        #pragma unroll 8
        for (int k = 0; k < 256; ++k)
            v = fmaf(H2f[k * 20 + p], decW3[k * 6 + o], v);
        raw[t] = v;
    }
    __syncthreads();

    // ---- params = proj[s] @ raw + def[s] -> g_par ----
    if (t < NPAR) {
        float v = defp[s * NPAR + t];
        const float* pr = proj + (size_t)s * NPAR * NPAR + t * NPAR;
        #pragma unroll 8
        for (int j = 0; j < NPAR; ++j)
            v = fmaf(pr[j], raw[j], v);
        g_par[bk * NPAR + t] = v;
    }
}

// ---------------------------------------------------------------------------
// Kernel 5: deformation pts = mat[s] @ params. grid (640, 6).
// ---------------------------------------------------------------------------
__global__ __launch_bounds__(256)
void k_deform(const float* __restrict__ mat, float* __restrict__ out)
{
    const int bk = blockIdx.x;
    const int t = threadIdx.x;
    const int s = g_idx[bk];
    __shared__ float par[NPAR];
    if (t < NPAR) par[t] = g_par[bk * NPAR + t];
    __syncthreads();

    const int r = blockIdx.y * 256 + t;
    const float* mr = mat + (size_t)s * PSRC3 * NPAR + (size_t)r * NPAR;
    float v = 0.f;
    #pragma unroll
    for (int j4 = 0; j4 < 24; ++j4) {
        float4 m4 = *(const float4*)&mr[j4 * 4];
        v = fmaf(m4.x, par[j4 * 4 + 0], v);
        v = fmaf(m4.y, par[j4 * 4 + 1], v);
        v = fmaf(m4.z, par[j4 * 4 + 2], v);
        v = fmaf(m4.w, par[j4 * 4 + 3], v);
    }
    out[(size_t)bk * PSRC3 + r] = v;
}

// ---------------------------------------------------------------------------
extern "C" void kernel_launch(void* const* d_in, const int* in_sizes, int n_in,
                              void* d_out, int out_size)
{
    const float* noc  = (const float*)d_in[0];
    const float* teW1 = (const float*)d_in[1];  const float* teb1 = (const float*)d_in[2];
    const float* teW2 = (const float*)d_in[3];  const float* teb2 = (const float*)d_in[4];
    const float* teW3 = (const float*)d_in[5];  const float* teb3 = (const float*)d_in[6];
    const float* teWf = (const float*)d_in[7];  const float* tebf = (const float*)d_in[8];
    const float* reW1 = (const float*)d_in[9];  const float* reb1 = (const float*)d_in[10];
    const float* reW2 = (const float*)d_in[11]; const float* reb2 = (const float*)d_in[12];
    const float* reW3 = (const float*)d_in[13]; const float* reb3 = (const float*)d_in[14];
    const float* reWf = (const float*)d_in[15]; const float* rebf = (const float*)d_in[16];
    const float* decW1 = (const float*)d_in[17]; const float* decb1 = (const float*)d_in[18];
    const float* decW2 = (const float*)d_in[19]; const float* decb2 = (const float*)d_in[20];
    const float* decW3 = (const float*)d_in[21]; const float* decb3 = (const float*)d_in[22];
    const float* ret_src = (const float*)d_in[23];
    const float* src_codes = (const float*)d_in[24];
    const float* src_var = (const float*)d_in[25];
    const float* part_latent = (const float*)d_in[26];
    const float* defp = (const float*)d_in[27];
    const float* proj = (const float*)d_in[28];
    const float* mat  = (const float*)d_in[29];
    float* out = (float*)d_out;

    dim3 gt(32, 8);
    dim3 bt(32, 8);
    k_transpose<<<gt, bt>>>(src_var, ret_src);
    k_preSC1<<<128, 256>>>(src_codes, decW1, decb1);
    dim3 g1(B_, 2, NQ);
    k_pointnet<<<g1, 256>>>(noc,
                            teW1, teb1, teW2, teb2, teW3, teb3,
                            reW1, reb1, reW2, reb2, reW3, reb3);
    k_preP1<<<S_, 256>>>(part_latent, decW1);
    k_fc<<<B_, 256>>>(teWf, tebf, reWf, rebf, decW1);
    k_dist<<<B_, 256>>>();
    k_decode_mlp<<<B_ * KRET, 256>>>(decW2, decb2, decW3, decb3, proj, defp);
    dim3 g5(B_ * KRET, 6);
    k_deform<<<g5, 256>>>(mat, out);
}

// round 9
// speedup vs baseline: 2.1456x; 1.3367x over previous
#include <cuda_runtime.h>
#include <cuda_bf16.h>
#include <cstdint>

// ---------------------------------------------------------------------------
// JointRetriveDeformHead — round 8
//  * tcgen05 is NOT compilable here (harness targets sm_103, no 'a' feature).
//    PointNet H3 moved to legacy mma.sync m16n8k16 bf16 (sm_80+ baseline PTX),
//    2-limb fp32 emulation: D += Ahi*Bhi + Ahi*Blo + Alo*Bhi.
//  * A(=W3^T) hi-limb fragments register-resident; lo-limb in smem (pad 136).
//  * D layout [chan x point] -> maxpool is per-thread register max + 2 shfls.
//  * H1/H2 exact fp32 scalar (round-5 code), H2 output split to bf16 limbs.
//  * Rest of pipeline = round-5 passing code.
// ---------------------------------------------------------------------------

#define B_      64
#define S_      1024
#define D_      256
#define KRET    10
#define NPART   16
#define NPAR    96
#define PSRC3   1536

__device__ float g_pool[2 * B_ * D_];
__device__ float g_ret [B_ * D_];
__device__ float g_T   [B_ * D_];
__device__ int   g_idx [B_ * KRET];
__device__ float g_par [B_ * KRET * NPAR];
__device__ float g_SC1 [S_ * D_];
__device__ float g_P1  [S_ * NPART * D_];
__device__ float g_varT[D_ * S_];
__device__ float g_rscT[D_ * S_];
__device__ unsigned short g_A3h[2 * 256 * 128];   // W3^T hi limb [enc][ch][k]
__device__ unsigned short g_A3l[2 * 256 * 128];   // W3^T lo limb

typedef unsigned long long u64;

__device__ __forceinline__ u64 pk(float lo, float hi) {
    u64 r; asm("mov.b64 %0,{%1,%2};" : "=l"(r) : "f"(lo), "f"(hi)); return r;
}
__device__ __forceinline__ void upk(u64 v, float& lo, float& hi) {
    asm("mov.b64 {%0,%1},%2;" : "=f"(lo), "=f"(hi) : "l"(v));
}
__device__ __forceinline__ u64 fma2(u64 a, u64 b, u64 c) {
    u64 d; asm("fma.rn.f32x2 %0,%1,%2,%3;" : "=l"(d) : "l"(a), "l"(b), "l"(c)); return d;
}
__device__ __forceinline__ void split_bf16(float v, unsigned short& h, unsigned short& l) {
    __nv_bfloat16 bh = __float2bfloat16(v);
    float fh = __bfloat162float(bh);
    __nv_bfloat16 bl = __float2bfloat16(v - fh);
    h = __bfloat16_as_ushort(bh);
    l = __bfloat16_as_ushort(bl);
}

#define MMA16816(d0,d1,d2,d3,a0,a1,a2,a3,b0,b1) \
    asm volatile("mma.sync.aligned.m16n8k16.row.col.f32.bf16.bf16.f32 " \
        "{%0,%1,%2,%3}, {%4,%5,%6,%7}, {%8,%9}, {%0,%1,%2,%3};" \
        : "+f"(d0),"+f"(d1),"+f"(d2),"+f"(d3) \
        : "r"(a0),"r"(a1),"r"(a2),"r"(a3),"r"(b0),"r"(b1))

// dynamic smem layout (bytes)
#define OFF_ALO 0          // u16 [256][136]  = 69632
#define OFF_BH  69632      // u16 [32][136]   = 8704
#define OFF_BL  78336      // u16 [32][136]   = 8704
#define OFF_H1  87040      // float [64][36]  = 9216
#define OFF_X   96256      // float [3][32]   = 384
#define SMEMSZ  96640

// ---------------------------------------------------------------------------
// Prepack: W3^T bf16 limbs, [enc][ch][k] contiguous-k. grid 256, 256 thr.
// ---------------------------------------------------------------------------
__global__ __launch_bounds__(256)
void k_prepackA(const float* __restrict__ teW3, const float* __restrict__ reW3)
{
    int idx = blockIdx.x * 256 + threadIdx.x;   // 65536
    int enc = idx >> 15;
    int r   = idx & 32767;
    int ch  = r >> 7;
    int k   = r & 127;
    const float* W3 = enc ? reW3 : teW3;
    float w = W3[k * 256 + ch];
    unsigned short h, l;
    split_bf16(w, h, l);
    g_A3h[idx] = h;
    g_A3l[idx] = l;
}

// ---------------------------------------------------------------------------
// Kernel A: transpose var & rsc to [k][s]
// ---------------------------------------------------------------------------
__global__ __launch_bounds__(256)
void k_transpose(const float* __restrict__ var, const float* __restrict__ rsc)
{
    __shared__ float tv[32][33];
    __shared__ float tr[32][33];
    const int tx = threadIdx.x, ty = threadIdx.y;
    const int s0 = blockIdx.x * 32, k0 = blockIdx.y * 32;
    #pragma unroll
    for (int jj = 0; jj < 4; ++jj) {
        int s = s0 + ty + jj * 8;
        tv[ty + jj * 8][tx] = var[s * D_ + k0 + tx];
        tr[ty + jj * 8][tx] = rsc[s * D_ + k0 + tx];
    }
    __syncthreads();
    #pragma unroll
    for (int jj = 0; jj < 4; ++jj) {
        int k = k0 + ty + jj * 8;
        g_varT[k * S_ + s0 + tx] = tv[tx][ty + jj * 8];
        g_rscT[k * S_ + s0 + tx] = tr[tx][ty + jj * 8];
    }
}

// ---------------------------------------------------------------------------
// Kernel C: SC1 for 8 sources per block
// ---------------------------------------------------------------------------
__global__ __launch_bounds__(256, 3)
void k_preSC1(const float* __restrict__ src_codes,
              const float* __restrict__ decW1, const float* __restrict__ decb1)
{
    const int s0 = blockIdx.x * 8, t = threadIdx.x;
    __shared__ float scs[8][256];
    #pragma unroll
    for (int q = 0; q < 8; ++q)
        scs[q][t] = src_codes[(s0 + q) * 256 + t];
    __syncthreads();

    float acc[8];
    float bb = decb1[t];
    #pragma unroll
    for (int q = 0; q < 8; ++q) acc[q] = bb;
    #pragma unroll 4
    for (int i = 0; i < 256; ++i) {
        float w = decW1[(256 + i) * 256 + t];
        #pragma unroll
        for (int q = 0; q < 8; ++q)
            acc[q] = fmaf(scs[q][i], w, acc[q]);
    }
    #pragma unroll
    for (int q = 0; q < 8; ++q)
        g_SC1[(s0 + q) * 256 + t] = acc[q];
}

// ---------------------------------------------------------------------------
// Kernel D: P1[s][p] = part[s,p] . W1tail
// ---------------------------------------------------------------------------
__global__ __launch_bounds__(256, 4)
void k_preP1(const float* __restrict__ part_latent, const float* __restrict__ decW1)
{
    const int s = blockIdx.x, t = threadIdx.x;
    __shared__ float part[NPART][32];
    ((float*)part)[t]       = part_latent[s * (NPART * 32) + t];
    ((float*)part)[t + 256] = part_latent[s * (NPART * 32) + t + 256];
    __syncthreads();

    float wt[32];
    #pragma unroll
    for (int i = 0; i < 32; ++i)
        wt[i] = decW1[(512 + i) * 256 + t];
    #pragma unroll 2
    for (int p = 0; p < NPART; ++p) {
        float v = 0.f;
        #pragma unroll
        for (int i = 0; i < 32; ++i)
            v = fmaf(part[p][i], wt[i], v);
        g_P1[(s * NPART + p) * 256 + t] = v;
    }
}

// ---------------------------------------------------------------------------
// Kernel 1: PointNet. grid (64,2), 256 threads, 1 CTA/SM, mma.sync H3.
// ---------------------------------------------------------------------------
__global__ __launch_bounds__(256, 1)
void k_pointnet(const float* __restrict__ noc,
                const float* __restrict__ teW1, const float* __restrict__ teb1,
                const float* __restrict__ teW2, const float* __restrict__ teb2,
                const float* __restrict__ teb3,
                const float* __restrict__ reW1, const float* __restrict__ reb1,
                const float* __restrict__ reW2, const float* __restrict__ reb2,
                const float* __restrict__ reb3)
{
    extern __shared__ char smem[];
    const int b = blockIdx.x;
    const int enc = blockIdx.y;
    const float* W1 = enc ? reW1 : teW1; const float* b1 = enc ? reb1 : teb1;
    const float* W2 = enc ? reW2 : teW2; const float* b2 = enc ? reb2 : teb2;
    const float* b3 = enc ? reb3 : teb3;

    const int t = threadIdx.x;
    const int warp = t >> 5, lane = t & 31;
    const int g = lane >> 2, j = lane & 3;

    unsigned short* ALO = (unsigned short*)(smem + OFF_ALO);
    unsigned short* BHs = (unsigned short*)(smem + OFF_BH);
    unsigned short* BLs = (unsigned short*)(smem + OFF_BL);
    float* H1c = (float*)(smem + OFF_H1);
    float* Xf  = (float*)(smem + OFF_X);
    const uint32_t* ALO32 = (const uint32_t*)ALO;
    const uint32_t* BH32  = (const uint32_t*)BHs;
    const uint32_t* BL32  = (const uint32_t*)BLs;

    // ---- stage A-lo limb into padded smem (row ch = thread t) ----
    {
        const uint4* src = (const uint4*)(g_A3l + enc * 32768);
        #pragma unroll
        for (int i = 0; i < 16; ++i)
            *(uint4*)(ALO + t * 136 + i * 8) = src[t * 16 + i];
    }

    // ---- A-hi fragments -> registers (64 u32/thread) ----
    uint32_t ahi[64];
    {
        const uint32_t* AH = (const uint32_t*)(g_A3h + enc * 32768); // [256][64]
        #pragma unroll
        for (int mt = 0; mt < 2; ++mt) {
            const int r0 = warp * 32 + mt * 16 + g;
            #pragma unroll
            for (int ks = 0; ks < 8; ++ks) {
                const int fi = (mt * 8 + ks) * 4;
                ahi[fi + 0] = AH[r0 * 64 + j + 8 * ks];
                ahi[fi + 1] = AH[(r0 + 8) * 64 + j + 8 * ks];
                ahi[fi + 2] = AH[r0 * 64 + j + 4 + 8 * ks];
                ahi[fi + 3] = AH[(r0 + 8) * 64 + j + 4 + 8 * ks];
            }
        }
    }

    // scalar-stage mappings (as round 5)
    const int colB = t & 63, pgB = t >> 6;          // H1: 64 ch x 4 pgroups(8 pts)
    const int c0C = (t & 31) * 4, pgC = t >> 5;     // H2: 32x4 ch x 8 pgroups(4 pts)
    const float w10 = W1[colB], w11 = W1[64 + colB], w12 = W1[128 + colB];
    const float bb1 = b1[colB];
    const float4 bb2 = *(const float4*)&b2[c0C];
    const u64 bb2p[4] = { pk(bb2.x, bb2.x), pk(bb2.y, bb2.y),
                          pk(bb2.z, bb2.z), pk(bb2.w, bb2.w) };

    float dmax[4] = { -1e30f, -1e30f, -1e30f, -1e30f };  // [mt][rowhalf]

    #pragma unroll 1
    for (int chunk = 0; chunk < 32; ++chunk) {
        __syncthreads();   // previous MMA reads of BH/BL done
        if (t < 96) {
            int c = t >> 5, p = t & 31;
            Xf[c * 32 + p] = noc[b * 3072 + c * 1024 + chunk * 32 + p];
        }
        __syncthreads();

        // ---- H1: 3 -> 64 ----
        {
            float v[8];
            #pragma unroll
            for (int pp = 0; pp < 8; ++pp) {
                int p = pgB * 8 + pp;
                float h = fmaf(Xf[p], w10, fmaf(Xf[32 + p], w11, fmaf(Xf[64 + p], w12, bb1)));
                v[pp] = fmaxf(h, 0.f);
            }
            #pragma unroll
            for (int q = 0; q < 4; ++q)
                *(u64*)&H1c[colB * 36 + pgB * 8 + 2 * q] = pk(v[2*q], v[2*q+1]);
        }
        __syncthreads();

        // ---- H2: 64 -> 128 (fp32 exact), relu, split limbs into B tiles ----
        {
            u64 acc[2][4];
            #pragma unroll
            for (int q = 0; q < 2; ++q)
                #pragma unroll
                for (int jj = 0; jj < 4; ++jj) acc[q][jj] = bb2p[jj];
            #pragma unroll 4
            for (int k = 0; k < 64; ++k) {
                ulonglong2 xa = *(const ulonglong2*)&H1c[k * 36 + pgC * 4];
                float4 w = *(const float4*)&W2[k * 128 + c0C];
                u64 wp0 = pk(w.x, w.x), wp1 = pk(w.y, w.y);
                u64 wp2 = pk(w.z, w.z), wp3 = pk(w.w, w.w);
                acc[0][0] = fma2(xa.x, wp0, acc[0][0]);
                acc[0][1] = fma2(xa.x, wp1, acc[0][1]);
                acc[0][2] = fma2(xa.x, wp2, acc[0][2]);
                acc[0][3] = fma2(xa.x, wp3, acc[0][3]);
                acc[1][0] = fma2(xa.y, wp0, acc[1][0]);
                acc[1][1] = fma2(xa.y, wp1, acc[1][1]);
                acc[1][2] = fma2(xa.y, wp2, acc[1][2]);
                acc[1][3] = fma2(xa.y, wp3, acc[1][3]);
            }
            float vals[4][4];
            #pragma unroll
            for (int q = 0; q < 2; ++q)
                #pragma unroll
                for (int jj = 0; jj < 4; ++jj)
                    upk(acc[q][jj], vals[2*q][jj], vals[2*q+1][jj]);
            #pragma unroll
            for (int p = 0; p < 4; ++p) {
                int n = pgC * 4 + p;
                unsigned short h[4], l[4];
                #pragma unroll
                for (int jj = 0; jj < 4; ++jj)
                    split_bf16(fmaxf(vals[p][jj], 0.f), h[jj], l[jj]);
                u64 hp = (u64)h[0] | ((u64)h[1] << 16) | ((u64)h[2] << 32) | ((u64)h[3] << 48);
                u64 lp = (u64)l[0] | ((u64)l[1] << 16) | ((u64)l[2] << 32) | ((u64)l[3] << 48);
                *(u64*)((char*)BHs + n * 272 + c0C * 2) = hp;
                *(u64*)((char*)BLs + n * 272 + c0C * 2) = lp;
            }
        }
        __syncthreads();

        // ---- MMA: D[256ch x 32pt] = W3^T limbs x H2 limbs ----
        float d[2][4][4];
        #pragma unroll
        for (int mt = 0; mt < 2; ++mt)
            #pragma unroll
            for (int nt = 0; nt < 4; ++nt)
                #pragma unroll
                for (int e = 0; e < 4; ++e) d[mt][nt][e] = 0.f;

        #pragma unroll
        for (int ks = 0; ks < 8; ++ks) {
            uint32_t bh0[4], bh1[4], bl0[4], bl1[4];
            #pragma unroll
            for (int nt = 0; nt < 4; ++nt) {
                const uint32_t* BHrow = BH32 + (nt * 8 + g) * 68;
                const uint32_t* BLrow = BL32 + (nt * 8 + g) * 68;
                bh0[nt] = BHrow[j + 8 * ks];
                bh1[nt] = BHrow[j + 4 + 8 * ks];
                bl0[nt] = BLrow[j + 8 * ks];
                bl1[nt] = BLrow[j + 4 + 8 * ks];
            }
            #pragma unroll
            for (int mt = 0; mt < 2; ++mt) {
                const int fi = (mt * 8 + ks) * 4;
                uint32_t a0 = ahi[fi], a1 = ahi[fi+1], a2 = ahi[fi+2], a3 = ahi[fi+3];
                #pragma unroll
                for (int nt = 0; nt < 4; ++nt) {
                    MMA16816(d[mt][nt][0], d[mt][nt][1], d[mt][nt][2], d[mt][nt][3],
                             a0, a1, a2, a3, bh0[nt], bh1[nt]);
                    MMA16816(d[mt][nt][0], d[mt][nt][1], d[mt][nt][2], d[mt][nt][3],
                             a0, a1, a2, a3, bl0[nt], bl1[nt]);
                }
                const int r0 = warp * 32 + mt * 16 + g;
                uint32_t l0 = ALO32[r0 * 68 + j + 8 * ks];
                uint32_t l1 = ALO32[(r0 + 8) * 68 + j + 8 * ks];
                uint32_t l2 = ALO32[r0 * 68 + j + 4 + 8 * ks];
                uint32_t l3 = ALO32[(r0 + 8) * 68 + j + 4 + 8 * ks];
                #pragma unroll
                for (int nt = 0; nt < 4; ++nt)
                    MMA16816(d[mt][nt][0], d[mt][nt][1], d[mt][nt][2], d[mt][nt][3],
                             l0, l1, l2, l3, bh0[nt], bh1[nt]);
            }
        }

        // running max (cols = points; rows = channels)
        #pragma unroll
        for (int mt = 0; mt < 2; ++mt)
            #pragma unroll
            for (int nt = 0; nt < 4; ++nt) {
                dmax[mt*2+0] = fmaxf(dmax[mt*2+0], fmaxf(d[mt][nt][0], d[mt][nt][1]));
                dmax[mt*2+1] = fmaxf(dmax[mt*2+1], fmaxf(d[mt][nt][2], d[mt][nt][3]));
            }
    }

    // reduce across the 4 threads sharing each channel row (j = 0..3)
    #pragma unroll
    for (int e = 0; e < 4; ++e) {
        dmax[e] = fmaxf(dmax[e], __shfl_xor_sync(0xffffffffu, dmax[e], 1));
        dmax[e] = fmaxf(dmax[e], __shfl_xor_sync(0xffffffffu, dmax[e], 2));
    }
    if (j == 0) {
        #pragma unroll
        for (int mt = 0; mt < 2; ++mt)
            #pragma unroll
            for (int hf = 0; hf < 2; ++hf) {
                int ch = warp * 32 + mt * 16 + hf * 8 + g;
                g_pool[(enc * B_ + b) * D_ + ch] = fmaxf(dmax[mt*2+hf] + b3[ch], 0.f);
            }
    }
}

// ---------------------------------------------------------------------------
// Kernel 2: final fc + T = tgt @ dec_W1[0:256]
// ---------------------------------------------------------------------------
__global__ __launch_bounds__(256, 1)
void k_fc(const float* __restrict__ teWf, const float* __restrict__ tebf,
          const float* __restrict__ reWf, const float* __restrict__ rebf,
          const float* __restrict__ decW1)
{
    const int b = blockIdx.x, t = threadIdx.x;
    __shared__ float ste[256], sre[256], stgt[256];
    ste[t] = g_pool[b * D_ + t];
    sre[t] = g_pool[(B_ + b) * D_ + t];
    __syncthreads();

    float a = tebf[t], r = rebf[t];
    #pragma unroll 8
    for (int i = 0; i < 256; ++i) {
        a = fmaf(ste[i], teWf[i * 256 + t], a);
        r = fmaf(sre[i], reWf[i * 256 + t], r);
    }
    g_ret[b * D_ + t] = r;
    stgt[t] = a;
    __syncthreads();

    float tv = 0.f;
    #pragma unroll 8
    for (int i = 0; i < 256; ++i)
        tv = fmaf(stgt[i], decW1[i * 256 + t], tv);
    g_T[b * D_ + t] = tv;
}

// ---------------------------------------------------------------------------
// Kernel 3: distances + exact top-10
// ---------------------------------------------------------------------------
__global__ __launch_bounds__(256, 1)
void k_dist()
{
    const int b = blockIdx.x, t = threadIdx.x;
    __shared__ float rets[256];
    __shared__ float d[1024];
    __shared__ float sval[256];
    __shared__ int   sidx[256];

    rets[t] = g_ret[b * D_ + t];
    __syncthreads();

    const int s4 = 4 * t;
    float a0 = 0.f, a1 = 0.f, a2 = 0.f, a3 = 0.f;
    #pragma unroll 4
    for (int k = 0; k < 256; ++k) {
        float r = rets[k];
        float4 v = *(const float4*)&g_varT[k * S_ + s4];
        float4 c = *(const float4*)&g_rscT[k * S_ + s4];
        float d0 = r - c.x, d1 = r - c.y, d2 = r - c.z, d3 = r - c.w;
        a0 = fmaf(v.x, d0 * d0, a0);
        a1 = fmaf(v.y, d1 * d1, a1);
        a2 = fmaf(v.z, d2 * d2, a2);
        a3 = fmaf(v.w, d3 * d3, a3);
    }
    d[s4] = a0; d[s4 + 1] = a1; d[s4 + 2] = a2; d[s4 + 3] = a3;
    __syncthreads();

    for (int it = 0; it < KRET; ++it) {
        float bv = 1e30f; int bi = S_;
        #pragma unroll
        for (int q = 0; q < 4; ++q) {
            int s = q * 256 + t;
            float v = d[s];
            if (v < bv || (v == bv && s < bi)) { bv = v; bi = s; }
        }
        sval[t] = bv; sidx[t] = bi;
        __syncthreads();
        for (int off = 128; off > 0; off >>= 1) {
            if (t < off) {
                float v2 = sval[t + off]; int i2 = sidx[t + off];
                if (v2 < sval[t] || (v2 == sval[t] && i2 < sidx[t])) {
                    sval[t] = v2; sidx[t] = i2;
                }
            }
            __syncthreads();
        }
        if (t == 0) {
            g_idx[b * KRET + it] = sidx[0];
            d[sidx[0]] = 1e30f;
        }
        __syncthreads();
    }
}

// ---------------------------------------------------------------------------
// Kernel 4: decoder MLP -> params[96] per (b,k). 4 CTAs/SM.
// ---------------------------------------------------------------------------
__global__ __launch_bounds__(256, 4)
void k_decode_mlp(const float* __restrict__ decW2, const float* __restrict__ decb2,
                  const float* __restrict__ decW3, const float* __restrict__ decb3,
                  const float* __restrict__ proj,  const float* __restrict__ defp)
{
    const int bk = blockIdx.x;
    const int b = bk / KRET;
    const int t = threadIdx.x;
    const int s = g_idx[bk];

    __shared__ __align__(16) u64 H1p[256][10];
    __shared__ __align__(16) u64 H2p[256][10];
    __shared__ float raw[NPAR];

    {
        float base = g_T[b * D_ + t] + g_SC1[s * 256 + t];
        const float* p1 = &g_P1[s * (NPART * 256) + t];
        #pragma unroll
        for (int pr = 0; pr < 8; ++pr) {
            float lo = fmaxf(base + p1[(2 * pr) * 256], 0.f);
            float hi = fmaxf(base + p1[(2 * pr + 1) * 256], 0.f);
            H1p[t][pr] = pk(lo, hi);
        }
    }
    __syncthreads();

    const int c0 = (t & 63) * 4, pg = t >> 6;

    {
        u64 acc[2][4];
        float4 bb = *(const float4*)&decb2[c0];
        acc[0][0] = acc[1][0] = pk(bb.x, bb.x);
        acc[0][1] = acc[1][1] = pk(bb.y, bb.y);
        acc[0][2] = acc[1][2] = pk(bb.z, bb.z);
        acc[0][3] = acc[1][3] = pk(bb.w, bb.w);
        #pragma unroll 4
        for (int k = 0; k < 256; ++k) {
            ulonglong2 xx = *(const ulonglong2*)&H1p[k][pg * 2];
            float4 w = *(const float4*)&decW2[k * 256 + c0];
            u64 wp0 = pk(w.x, w.x), wp1 = pk(w.y, w.y);
            u64 wp2 = pk(w.z, w.z), wp3 = pk(w.w, w.w);
            acc[0][0] = fma2(xx.x, wp0, acc[0][0]);
            acc[0][1] = fma2(xx.x, wp1, acc[0][1]);
            acc[0][2] = fma2(xx.x, wp2, acc[0][2]);
            acc[0][3] = fma2(xx.x, wp3, acc[0][3]);
            acc[1][0] = fma2(xx.y, wp0, acc[1][0]);
            acc[1][1] = fma2(xx.y, wp1, acc[1][1]);
            acc[1][2] = fma2(xx.y, wp2, acc[1][2]);
            acc[1][3] = fma2(xx.y, wp3, acc[1][3]);
        }
        #pragma unroll
        for (int jj = 0; jj < 4; ++jj) {
            #pragma unroll
            for (int q = 0; q < 2; ++q) {
                float lo, hi; upk(acc[q][jj], lo, hi);
                lo = fmaxf(lo, 0.f); hi = fmaxf(hi, 0.f);
                H2p[c0 + jj][pg * 2 + q] = pk(lo, hi);
            }
        }
    }
    __syncthreads();

    const float* H2f = (const float*)H2p;
    if (t < NPAR) {
        const int p = t / 6, o = t % 6;
        float v = decb3[o];
        #pragma unroll 8
        for (int k = 0; k < 256; ++k)
            v = fmaf(H2f[k * 20 + p], decW3[k * 6 + o], v);
        raw[t] = v;
    }
    __syncthreads();

    if (t < NPAR) {
        float v = defp[s * NPAR + t];
        const float* pr = proj + (size_t)s * NPAR * NPAR + t * NPAR;
        #pragma unroll 8
        for (int jj = 0; jj < NPAR; ++jj)
            v = fmaf(pr[jj], raw[jj], v);
        g_par[bk * NPAR + t] = v;
    }
}

// ---------------------------------------------------------------------------
// Kernel 5: deformation pts = mat[s] @ params. grid (640, 6).
// ---------------------------------------------------------------------------
__global__ __launch_bounds__(256)
void k_deform(const float* __restrict__ mat, float* __restrict__ out)
{
    const int bk = blockIdx.x;
    const int t = threadIdx.x;
    const int s = g_idx[bk];
    __shared__ float par[NPAR];
    if (t < NPAR) par[t] = g_par[bk * NPAR + t];
    __syncthreads();

    const int r = blockIdx.y * 256 + t;
    const float* mr = mat + (size_t)s * PSRC3 * NPAR + (size_t)r * NPAR;
    float v = 0.f;
    #pragma unroll
    for (int j4 = 0; j4 < 24; ++j4) {
        float4 m4 = *(const float4*)&mr[j4 * 4];
        v = fmaf(m4.x, par[j4 * 4 + 0], v);
        v = fmaf(m4.y, par[j4 * 4 + 1], v);
        v = fmaf(m4.z, par[j4 * 4 + 2], v);
        v = fmaf(m4.w, par[j4 * 4 + 3], v);
    }
    out[(size_t)bk * PSRC3 + r] = v;
}

// ---------------------------------------------------------------------------
extern "C" void kernel_launch(void* const* d_in, const int* in_sizes, int n_in,
                              void* d_out, int out_size)
{
    const float* noc  = (const float*)d_in[0];
    const float* teW1 = (const float*)d_in[1];  const float* teb1 = (const float*)d_in[2];
    const float* teW2 = (const float*)d_in[3];  const float* teb2 = (const float*)d_in[4];
    const float* teW3 = (const float*)d_in[5];  const float* teb3 = (const float*)d_in[6];
    const float* teWf = (const float*)d_in[7];  const float* tebf = (const float*)d_in[8];
    const float* reW1 = (const float*)d_in[9];  const float* reb1 = (const float*)d_in[10];
    const float* reW2 = (const float*)d_in[11]; const float* reb2 = (const float*)d_in[12];
    const float* reW3 = (const float*)d_in[13]; const float* reb3 = (const float*)d_in[14];
    const float* reWf = (const float*)d_in[15]; const float* rebf = (const float*)d_in[16];
    const float* decW1 = (const float*)d_in[17]; const float* decb1 = (const float*)d_in[18];
    const float* decW2 = (const float*)d_in[19]; const float* decb2 = (const float*)d_in[20];
    const float* decW3 = (const float*)d_in[21]; const float* decb3 = (const float*)d_in[22];
    const float* ret_src = (const float*)d_in[23];
    const float* src_codes = (const float*)d_in[24];
    const float* src_var = (const float*)d_in[25];
    const float* part_latent = (const float*)d_in[26];
    const float* defp = (const float*)d_in[27];
    const float* proj = (const float*)d_in[28];
    const float* mat  = (const float*)d_in[29];
    float* out = (float*)d_out;

    cudaFuncSetAttribute(k_pointnet, cudaFuncAttributeMaxDynamicSharedMemorySize, SMEMSZ);

    dim3 gt(32, 8), bt(32, 8);
    k_transpose<<<gt, bt>>>(src_var, ret_src);
    k_prepackA<<<256, 256>>>(teW3, reW3);
    k_preSC1<<<128, 256>>>(src_codes, decW1, decb1);
    dim3 g1(B_, 2);
    k_pointnet<<<g1, 256, SMEMSZ>>>(noc,
                                    teW1, teb1, teW2, teb2, teb3,
                                    reW1, reb1, reW2, reb2, reb3);
    k_preP1<<<S_, 256>>>(part_latent, decW1);
    k_fc<<<B_, 256>>>(teWf, tebf, reWf, rebf, decW1);
    k_dist<<<B_, 256>>>();
    k_decode_mlp<<<B_ * KRET, 256>>>(decW2, decb2, decW3, decb3, proj, defp);
    dim3 g5(B_ * KRET, 6);
    k_deform<<<g5, 256>>>(mat, out);
}